// round 1
// baseline (speedup 1.0000x reference)
#include <cuda_runtime.h>

#define EN 160000      // edges = N*K
#define NN 10000       // nodes
#define NTILES (EN/128)

// Scratch (static device memory; no allocation at runtime)
__device__ float g_hT[NTILES * 64 * 128];    // per 128-edge tile, layout [j][e_local]
__device__ float g_tmpT[NTILES * 16 * 128];  // per 128-edge tile, layout [i][e_local]
__device__ float g_kqv[(size_t)EN * 96];     // per edge: 24 m2-rows x 4 dims (k:0-7,q:8-15,v:16-23)

// ---------------- Kernel 0: h = relu(edge_feats @ W1^T + b1), stored tile-transposed --------
__global__ void k_mlp1(const float* __restrict__ ef, const float* __restrict__ W1,
                       const float* __restrict__ b1) {
    __shared__ float sW1[64 * 32];
    __shared__ float sEF[32 * 32];
    int tid = threadIdx.x;
    int e0 = blockIdx.x * 32;
    for (int r = tid; r < 2048; r += 128) sW1[r] = W1[r];
    for (int r = tid; r < 1024; r += 128) sEF[r] = ef[e0 * 32 + r];
    __syncthreads();
    int el = tid >> 2;       // local edge 0..31
    int part = tid & 3;      // j-quarter
    float efr[32];
#pragma unroll
    for (int c = 0; c < 32; c++) efr[c] = sEF[el * 32 + c];
    int e = e0 + el;
    int tile = e >> 7, elocal = e & 127;
    float* dst = g_hT + (size_t)tile * (64 * 128) + elocal;
#pragma unroll
    for (int jj = 0; jj < 16; jj++) {
        int j = part * 16 + jj;
        float acc = __ldg(&b1[j]);
        const float* w = &sW1[j * 32];
#pragma unroll
        for (int c = 0; c < 32; c++) acc = fmaf(efr[c], w[c], acc);
        dst[j * 128] = fmaxf(acc, 0.0f);
    }
}

// ---------------- Kernel 0b: tmp[e, m*2+l] = sum_d f[src[e],m,d]*basis1[e,d,l] ---------------
__global__ void k_tmp(const float* __restrict__ basis1, const float* __restrict__ f,
                      const int* __restrict__ nbr) {
    int e = blockIdx.x * 128 + threadIdx.x;   // exact: 1250*128 = EN
    int src = nbr[e];
    const float4* fp = (const float4*)(f + (size_t)src * 32);
    float fr[8][4];
#pragma unroll
    for (int m = 0; m < 8; m++) {
        float4 v = __ldg(&fp[m]);
        fr[m][0] = v.x; fr[m][1] = v.y; fr[m][2] = v.z; fr[m][3] = v.w;
    }
    float4 b0 = __ldg((const float4*)(basis1 + (size_t)e * 8));
    float4 b1v = __ldg((const float4*)(basis1 + (size_t)e * 8 + 4));
    float bd[4][2] = {{b0.x, b0.y}, {b0.z, b0.w}, {b1v.x, b1v.y}, {b1v.z, b1v.w}};
    int tile = e >> 7, elocal = e & 127;
    float* dst = g_tmpT + (size_t)tile * (16 * 128) + elocal;
#pragma unroll
    for (int m = 0; m < 8; m++) {
#pragma unroll
        for (int l = 0; l < 2; l++) {
            float a = fr[m][0] * bd[0][l];
            a = fmaf(fr[m][1], bd[1][l], a);
            a = fmaf(fr[m][2], bd[2][l], a);
            a = fmaf(fr[m][3], bd[3][l], a);
            dst[(m * 2 + l) * 128] = a;
        }
    }
}

// ---------------- Kernel A: main bilinear contraction + kqv epilogue ------------------------
// Block: 128 threads, 128 edges. acc tile per thread: 4 edges x 12 o-outputs.
// tmp2[e,o] = sum_i tmp[e,i] * (sum_j W2[o*16+i, j] * h[e,j]) + sum_i b2[o*16+i]*tmp[e,i]
// kqv[e,m2,d] = tmp2[e,2*m2]*basis2[e,0,d] + tmp2[e,2*m2+1]*basis2[e,1,d]
__global__ void __launch_bounds__(128, 4) k_main(const float* __restrict__ W2,
                                                 const float* __restrict__ b2,
                                                 const float* __restrict__ basis2) {
    extern __shared__ float sm[];
    float* sHT  = sm;                      // [64][128]  8192 f
    float* sTMP = sm + 64 * 128;           // [16][128]  2048 f
    float* sB   = sm + 64 * 128 + 16 * 128; // [48][64]   3072 f  (o-major, row = W2 row)
    int tid = threadIdx.x;
    int blk = blockIdx.x;

    {   // coalesced tile copies (upstream kernels already wrote transposed tiles)
        const float4* src = (const float4*)(g_hT + (size_t)blk * (64 * 128));
        float4* d4 = (float4*)sHT;
#pragma unroll
        for (int r = 0; r < 16; r++) d4[tid + r * 128] = src[tid + r * 128];
        const float4* ts = (const float4*)(g_tmpT + (size_t)blk * (16 * 128));
        float4* t4p = (float4*)sTMP;
#pragma unroll
        for (int r = 0; r < 4; r++) t4p[tid + r * 128] = ts[tid + r * 128];
    }
    __syncthreads();

    int eg = tid & 31, og = tid >> 5;
    int eb = eg * 4;         // local edge base (4 edges)
    int ob = og * 12;        // o base (12 outputs), ob even -> complete (m2,l) pairs

    float acc[4][12];
#pragma unroll
    for (int a = 0; a < 4; a++)
#pragma unroll
        for (int b = 0; b < 12; b++) acc[a][b] = 0.0f;

    // bias contribution: acc[e,o] += sum_i b2[(ob+o)*16+i] * tmp[e,i]
#pragma unroll
    for (int i = 0; i < 16; i++) {
        float4 t4 = *(const float4*)&sTMP[i * 128 + eb];
#pragma unroll
        for (int o = 0; o < 12; o++) {
            float bb = __ldg(&b2[(ob + o) * 16 + i]);
            acc[0][o] = fmaf(t4.x, bb, acc[0][o]);
            acc[1][o] = fmaf(t4.y, bb, acc[1][o]);
            acc[2][o] = fmaf(t4.z, bb, acc[2][o]);
            acc[3][o] = fmaf(t4.w, bb, acc[3][o]);
        }
    }

    for (int i = 0; i < 16; i++) {
        __syncthreads();     // protect sB from previous iteration's readers
        // stage B_i = W2[o*16+i, :]  (48 rows x 64): 768 float4 / 128 threads = 6 each
#pragma unroll
        for (int r = 0; r < 6; r++) {
            int f4 = tid + r * 128;
            int o = f4 >> 4, j4 = f4 & 15;
            float4 v = __ldg((const float4*)(W2 + (size_t)(o * 16 + i) * 64 + j4 * 4));
            *(float4*)&sB[o * 64 + j4 * 4] = v;
        }
        __syncthreads();
        float4 t4 = *(const float4*)&sTMP[i * 128 + eb];
        const float* bp = sB + ob * 64;
#pragma unroll 2
        for (int j = 0; j < 64; j++) {
            float4 h4 = *(const float4*)&sHT[j * 128 + eb];
            float th0 = h4.x * t4.x, th1 = h4.y * t4.y;
            float th2 = h4.z * t4.z, th3 = h4.w * t4.w;
#pragma unroll
            for (int o = 0; o < 12; o++) {
                float bb = bp[o * 64 + j];            // warp-uniform broadcast
                acc[0][o] = fmaf(th0, bb, acc[0][o]);
                acc[1][o] = fmaf(th1, bb, acc[1][o]);
                acc[2][o] = fmaf(th2, bb, acc[2][o]);
                acc[3][o] = fmaf(th3, bb, acc[3][o]);
            }
        }
    }

    // epilogue: contract (m2, l) pairs with basis2 -> kqv
    int m2b = ob >> 1;  // 6 m2 rows per thread
#pragma unroll
    for (int er = 0; er < 4; er++) {
        int e = blk * 128 + eb + er;
        float4 p0 = __ldg((const float4*)(basis2 + (size_t)e * 8));      // basis2[e,0,:]
        float4 p1 = __ldg((const float4*)(basis2 + (size_t)e * 8 + 4));  // basis2[e,1,:]
        float* outp = g_kqv + (size_t)e * 96;
#pragma unroll
        for (int mm = 0; mm < 6; mm++) {
            float t0 = acc[er][mm * 2], t1 = acc[er][mm * 2 + 1];
            float4 kv;
            kv.x = fmaf(t0, p0.x, t1 * p1.x);
            kv.y = fmaf(t0, p0.y, t1 * p1.y);
            kv.z = fmaf(t0, p0.z, t1 * p1.z);
            kv.w = fmaf(t0, p0.w, t1 * p1.w);
            *(float4*)&outp[(m2b + mm) * 4] = kv;
        }
    }
}

// ---------------- Kernel B: per-node attention (warp per node) ------------------------------
__global__ void k_attn(float* __restrict__ out) {
    int warp = threadIdx.x >> 5, lane = threadIdx.x & 31;
    int n = blockIdx.x * 4 + warp;                 // grid 2500 * 4 warps = NN exact
    int k = lane & 15, rep = lane >> 4;            // rep covers heads {2rep, 2rep+1} = flats [16rep,16rep+16)
    const float* base = g_kqv + (size_t)(n * 16 + k) * 96 + rep * 16;
    float kk[16], qq[16], vv[16];
#pragma unroll
    for (int r = 0; r < 4; r++) {
        float4 a = *(const float4*)(base + r * 4);          // k part (offset 0)
        kk[r*4]=a.x; kk[r*4+1]=a.y; kk[r*4+2]=a.z; kk[r*4+3]=a.w;
        float4 b = *(const float4*)(base + 32 + r * 4);     // q part
        qq[r*4]=b.x; qq[r*4+1]=b.y; qq[r*4+2]=b.z; qq[r*4+3]=b.w;
        float4 c = *(const float4*)(base + 64 + r * 4);     // v part
        vv[r*4]=c.x; vv[r*4+1]=c.y; vv[r*4+2]=c.z; vv[r*4+3]=c.w;
    }
    // q_node = sum over the 16 k-lanes (xor<16 stays within rep group)
#pragma unroll
    for (int x = 0; x < 16; x++) {
        float q = qq[x];
        q += __shfl_xor_sync(0xffffffffu, q, 1);
        q += __shfl_xor_sync(0xffffffffu, q, 2);
        q += __shfl_xor_sync(0xffffffffu, q, 4);
        q += __shfl_xor_sync(0xffffffffu, q, 8);
        qq[x] = q;
    }
    const float scale = 0.35355339059327373f * 0.0625f;  // 8^-0.5 (attn) * 1/16 (q mean)
    float s0 = 0.f, s1 = 0.f;
#pragma unroll
    for (int x = 0; x < 8; x++) {
        s0 = fmaf(qq[x], kk[x], s0);
        s1 = fmaf(qq[8 + x], kk[8 + x], s1);
    }
    s0 *= scale; s1 *= scale;
    float m0 = s0, m1 = s1;
#pragma unroll
    for (int d = 1; d < 16; d <<= 1) {
        m0 = fmaxf(m0, __shfl_xor_sync(0xffffffffu, m0, d));
        m1 = fmaxf(m1, __shfl_xor_sync(0xffffffffu, m1, d));
    }
    float w0 = __expf(s0 - m0), w1 = __expf(s1 - m1);
    float z0 = w0, z1 = w1;
#pragma unroll
    for (int d = 1; d < 16; d <<= 1) {
        z0 += __shfl_xor_sync(0xffffffffu, z0, d);
        z1 += __shfl_xor_sync(0xffffffffu, z1, d);
    }
    w0 /= z0; w1 /= z1;
    float o[16];
#pragma unroll
    for (int x = 0; x < 8; x++) { o[x] = w0 * vv[x]; o[8 + x] = w1 * vv[8 + x]; }
#pragma unroll
    for (int x = 0; x < 16; x++) {
        float v = o[x];
        v += __shfl_xor_sync(0xffffffffu, v, 1);
        v += __shfl_xor_sync(0xffffffffu, v, 2);
        v += __shfl_xor_sync(0xffffffffu, v, 4);
        v += __shfl_xor_sync(0xffffffffu, v, 8);
        o[x] = v;
    }
    if (k == 0) {
        float* op = out + (size_t)n * 32 + rep * 16;
#pragma unroll
        for (int r = 0; r < 4; r++)
            *(float4*)(op + r * 4) = make_float4(o[r*4], o[r*4+1], o[r*4+2], o[r*4+3]);
    }
}

extern "C" void kernel_launch(void* const* d_in, const int* in_sizes, int n_in,
                              void* d_out, int out_size) {
    const float* basis1 = (const float*)d_in[0];   // (E,4,2)
    const float* basis2 = (const float*)d_in[1];   // (E,2,4)
    const float* ef     = (const float*)d_in[2];   // (E,32)
    const float* f      = (const float*)d_in[3];   // (N,8,4)
    const float* W1     = (const float*)d_in[4];   // (64,32)
    const float* b1     = (const float*)d_in[5];   // (64)
    const float* W2     = (const float*)d_in[6];   // (768,64)
    const float* b2     = (const float*)d_in[7];   // (768)
    const int*   nbr    = (const int*)d_in[8];     // (N,16)
    float* out = (float*)d_out;                    // (N,8,4)

    // idempotent, not a stream op — safe under graph capture
    cudaFuncSetAttribute(k_main, cudaFuncAttributeMaxDynamicSharedMemorySize, 53248);

    k_mlp1<<<EN / 32, 128>>>(ef, W1, b1);
    k_tmp<<<EN / 128, 128>>>(basis1, f, nbr);
    k_main<<<EN / 128, 128, 53248>>>(W2, b2, basis2);
    k_attn<<<NN / 4, 128>>>(out);
}

// round 3
// speedup vs baseline: 1.6089x; 1.6089x over previous
#include <cuda_runtime.h>
#include <cuda_bf16.h>
#include <cstdint>

#define EN 160000      // edges = N*K
#define NN 10000       // nodes
#define NTILES 1250    // EN/128

// ---------------- static device scratch -----------------------------------------------------
__device__ __align__(16) unsigned char g_Ahi[(size_t)NTILES * 16384]; // h hi: per-128-edge tile, [128 rows x 128B], SW128
__device__ __align__(16) unsigned char g_Alo[(size_t)NTILES * 16384]; // h lo
__device__ __align__(16) uint2 g_Bfhi[12 * 1024];   // W2 hi, m16n8k16 B-fragment layout: [chunk][kt][nt][lane]
__device__ __align__(16) uint2 g_Bflo[12 * 1024];   // W2 lo
__device__ float g_tmpT[NTILES * 16 * 128];         // per tile [i][e_local]
__device__ float g_kqv[(size_t)24 * EN * 4];        // plane-transposed: [m2][edge][dim]

// ---------------- helpers --------------------------------------------------------------------
__device__ __forceinline__ uint32_t smem_u32(const void* p) {
    uint32_t a;
    asm("{ .reg .u64 t; cvta.to.shared.u64 t, %1; cvt.u32.u64 %0, t; }" : "=r"(a) : "l"(p));
    return a;
}
#define SW128(o) ((o) ^ (((o) >> 3) & 0x70))

__device__ __forceinline__ void ldm_x4(uint32_t* r, uint32_t addr) {
    asm volatile("ldmatrix.sync.aligned.m8n8.x4.shared.b16 {%0,%1,%2,%3}, [%4];"
        : "=r"(r[0]), "=r"(r[1]), "=r"(r[2]), "=r"(r[3]) : "r"(addr));
}
__device__ __forceinline__ void mma16816(float* c, const uint32_t* a, const uint32_t* b) {
    asm volatile("mma.sync.aligned.m16n8k16.row.col.f32.bf16.bf16.f32 "
        "{%0,%1,%2,%3}, {%4,%5,%6,%7}, {%8,%9}, {%0,%1,%2,%3};"
        : "+f"(c[0]), "+f"(c[1]), "+f"(c[2]), "+f"(c[3])
        : "r"(a[0]), "r"(a[1]), "r"(a[2]), "r"(a[3]), "r"(b[0]), "r"(b[1]));
}
__device__ __forceinline__ void cpa16(uint32_t dst, const void* src) {
    asm volatile("cp.async.cg.shared.global [%0], [%1], 16;" :: "r"(dst), "l"(src));
}
#define CP_COMMIT() asm volatile("cp.async.commit_group;" ::: "memory")
#define CP_WAIT(n)  asm volatile("cp.async.wait_group %0;" :: "n"(n) : "memory")

__device__ __forceinline__ void split2(float a, float b, uint32_t& h, uint32_t& l) {
    __nv_bfloat16 ah = __float2bfloat16(a), bh = __float2bfloat16(b);
    __nv_bfloat16 al = __float2bfloat16(a - __bfloat162float(ah));
    __nv_bfloat16 bl = __float2bfloat16(b - __bfloat162float(bh));
    h = (uint32_t)__bfloat16_as_ushort(ah) | ((uint32_t)__bfloat16_as_ushort(bh) << 16);
    l = (uint32_t)__bfloat16_as_ushort(al) | ((uint32_t)__bfloat16_as_ushort(bl) << 16);
}

union Pack8 { __nv_bfloat16 b[8]; uint4 u; };

// ---------------- Kernel W: pack W2 into m16n8k16 B-fragment layout, split hi/lo -------------
// C[e,r] = sum_j h[e,j]*W2[r,j]  =>  B[k=j][n=r].  Fragment (thread l): b0 = B[2(l&3)+{0,1}][l>>2],
// b1 = same k+8. Stored per (chunk c, ktile kt, ntile nt): rows r = c*64+nt*8+(l>>2), j0 = kt*16+(l&3)*2.
__global__ void k_wprep(const float* __restrict__ W2) {
    int c = blockIdx.x, tid = threadIdx.x;
    for (int idx = tid; idx < 1024; idx += 128) {
        int kt = idx >> 8, nt = (idx >> 5) & 7, l = idx & 31;
        int row = c * 64 + nt * 8 + (l >> 2);
        int j0 = kt * 16 + (l & 3) * 2;
        const float* wr = W2 + (size_t)row * 64;
        uint32_t h0, l0, h1, l1;
        split2(__ldg(&wr[j0]),     __ldg(&wr[j0 + 1]), h0, l0);
        split2(__ldg(&wr[j0 + 8]), __ldg(&wr[j0 + 9]), h1, l1);
        g_Bfhi[c * 1024 + idx] = make_uint2(h0, h1);
        g_Bflo[c * 1024 + idx] = make_uint2(l0, l1);
    }
}

// ---------------- Kernel 0: h = relu(ef @ W1^T + b1) -> bf16 hi/lo swizzled A tiles ----------
__global__ void k_mlp1(const float* __restrict__ ef, const float* __restrict__ W1,
                       const float* __restrict__ b1) {
    __shared__ float sW1[64 * 32];
    __shared__ float sEF[32 * 32];
    int tid = threadIdx.x;
    int e0 = blockIdx.x * 32;
    for (int r = tid; r < 2048; r += 128) sW1[r] = W1[r];
    for (int r = tid; r < 1024; r += 128) sEF[r] = ef[e0 * 32 + r];
    __syncthreads();
    int el = tid >> 2;       // local edge 0..31
    int part = tid & 3;      // j-quarter (16 j each)
    float efr[32];
#pragma unroll
    for (int c = 0; c < 32; c++) efr[c] = sEF[el * 32 + c];
    int e = e0 + el;
    int tile = e >> 7, elt = e & 127;
    Pack8 h0, h1, l0, l1;
#pragma unroll
    for (int jj = 0; jj < 16; jj++) {
        int j = part * 16 + jj;
        float acc = __ldg(&b1[j]);
        const float* w = &sW1[j * 32];
#pragma unroll
        for (int c = 0; c < 32; c++) acc = fmaf(efr[c], w[c], acc);
        float x = fmaxf(acc, 0.0f);
        __nv_bfloat16 hb = __float2bfloat16(x);
        __nv_bfloat16 lb = __float2bfloat16(x - __bfloat162float(hb));
        if (jj < 8) { h0.b[jj] = hb; l0.b[jj] = lb; }
        else        { h1.b[jj - 8] = hb; l1.b[jj - 8] = lb; }
    }
    size_t tb = (size_t)tile * 16384;
    uint32_t o0 = elt * 128 + part * 32;
    uint32_t s0 = SW128(o0), s1 = SW128(o0 + 16);
    *(uint4*)(g_Ahi + tb + s0) = h0.u;
    *(uint4*)(g_Ahi + tb + s1) = h1.u;
    *(uint4*)(g_Alo + tb + s0) = l0.u;
    *(uint4*)(g_Alo + tb + s1) = l1.u;
}

// ---------------- Kernel 0b: tmp[e, m*2+l] = sum_d f[src[e],m,d]*basis1[e,d,l] ---------------
__global__ void k_tmp(const float* __restrict__ basis1, const float* __restrict__ f,
                      const int* __restrict__ nbr) {
    int e = blockIdx.x * 128 + threadIdx.x;
    int src = nbr[e];
    const float4* fp = (const float4*)(f + (size_t)src * 32);
    float fr[8][4];
#pragma unroll
    for (int m = 0; m < 8; m++) {
        float4 v = __ldg(&fp[m]);
        fr[m][0] = v.x; fr[m][1] = v.y; fr[m][2] = v.z; fr[m][3] = v.w;
    }
    float4 b0 = __ldg((const float4*)(basis1 + (size_t)e * 8));
    float4 b1v = __ldg((const float4*)(basis1 + (size_t)e * 8 + 4));
    float bd[4][2] = {{b0.x, b0.y}, {b0.z, b0.w}, {b1v.x, b1v.y}, {b1v.z, b1v.w}};
    int tile = e >> 7, elt = e & 127;
    float* dst = g_tmpT + (size_t)tile * (16 * 128) + elt;
#pragma unroll
    for (int m = 0; m < 8; m++)
#pragma unroll
        for (int l = 0; l < 2; l++) {
            float a = fr[m][0] * bd[0][l];
            a = fmaf(fr[m][1], bd[1][l], a);
            a = fmaf(fr[m][2], bd[2][l], a);
            a = fmaf(fr[m][3], bd[3][l], a);
            dst[(m * 2 + l) * 128] = a;
        }
}

// ---------------- Kernel A: HMMA GEMM C = h @ W2^T (split bf16), fused epilogue --------------
// CTA = 128 edges, 4 warps; warp w owns edges [32w,32w+32). 12 chunks x 64 W2-rows.
// acc[mt][nt][4]: 2 m16 tiles x 8 n8 tiles. Epilogue: C -> smem -> per-edge contraction with
// tmp (16) + bias, then basis2 -> plane-transposed kqv store.
#define S_AHI  0u
#define S_ALO  16384u
#define S_B    32768u          // two 16KB bufs: hi at +0, lo at +8192
#define S_C    65536u          // 128 x 66 fp32 (padded)
#define S_TMP  99328u          // 16 x 128 fp32
#define S_B2   107520u         // 768 fp32
#define SMEM_SZ (110592u + 1024u)

__global__ void __launch_bounds__(128) k_main(const float* __restrict__ b2,
                                              const float* __restrict__ basis2) {
    extern __shared__ unsigned char smraw[];
    uint32_t base = (smem_u32(smraw) + 1023u) & ~1023u;
    unsigned char* sm = smraw + (base - smem_u32(smraw));
    float* sCf = (float*)(sm + S_C);
    const float* sTMPf = (const float*)(sm + S_TMP);
    const float* sB2f = (const float*)(sm + S_B2);
    int tid = threadIdx.x, blk = blockIdx.x;
    int wid = tid >> 5, lane = tid & 31;

    // ---- prologue: async copies (group0 = A + B0 + tmp + b2; group1 = B1) ----
    {
        const uint4* gA = (const uint4*)(g_Ahi + (size_t)blk * 16384);
        const uint4* gL = (const uint4*)(g_Alo + (size_t)blk * 16384);
        for (int r = tid; r < 1024; r += 128) cpa16(base + S_AHI + r * 16, gA + r);
        for (int r = tid; r < 1024; r += 128) cpa16(base + S_ALO + r * 16, gL + r);
        const uint4* bh = (const uint4*)g_Bfhi;
        const uint4* bl = (const uint4*)g_Bflo;
        for (int r = tid; r < 512; r += 128) cpa16(base + S_B + r * 16, bh + r);
        for (int r = tid; r < 512; r += 128) cpa16(base + S_B + 8192 + r * 16, bl + r);
        const uint4* gt = (const uint4*)(g_tmpT + (size_t)blk * 2048);
        for (int r = tid; r < 512; r += 128) cpa16(base + S_TMP + r * 16, gt + r);
        const uint4* g2 = (const uint4*)b2;
        for (int r = tid; r < 192; r += 128) cpa16(base + S_B2 + r * 16, g2 + r);
        CP_COMMIT();
        for (int r = tid; r < 512; r += 128) cpa16(base + S_B + 16384 + r * 16, bh + 512 + r);
        for (int r = tid; r < 512; r += 128) cpa16(base + S_B + 16384 + 8192 + r * 16, bl + 512 + r);
        CP_COMMIT();
    }
    // basis2 for this thread's edge
    int e = blk * 128 + tid;
    float4 p0 = __ldg((const float4*)(basis2 + (size_t)e * 8));
    float4 p1 = __ldg((const float4*)(basis2 + (size_t)e * 8 + 4));

    // ldmatrix per-thread base byte offset within the A tile (add mt*2048 + kt*32)
    uint32_t rowOff = (uint32_t)(wid * 32 + (lane & 7) + 8 * ((lane >> 3) & 1)) * 128u
                    + 16u * (uint32_t)(lane >> 4);

    float acc[2][8][4];
#pragma unroll
    for (int mt = 0; mt < 2; mt++)
#pragma unroll
        for (int nt = 0; nt < 8; nt++)
#pragma unroll
            for (int x = 0; x < 4; x++) acc[mt][nt][x] = 0.0f;

    for (int c = 0; c < 12; c++) {
        if (c < 11) CP_WAIT(1); else CP_WAIT(0);
        __syncthreads();
        uint32_t sB = base + S_B + (uint32_t)(c & 1) * 16384u;

#pragma unroll
        for (int kt = 0; kt < 4; kt++) {
            uint32_t ah[2][4], al[2][4];
#pragma unroll
            for (int mt = 0; mt < 2; mt++) {
                uint32_t o = rowOff + (uint32_t)mt * 2048u + (uint32_t)kt * 32u;
                uint32_t so = SW128(o);
                ldm_x4(ah[mt], base + S_AHI + so);
                ldm_x4(al[mt], base + S_ALO + so);
            }
#pragma unroll
            for (int nt = 0; nt < 8; nt++) {
                uint32_t boff = (uint32_t)(((kt * 8 + nt) * 32 + lane) * 8);
                uint2 bh = *(const uint2*)(sm + sB - base + boff);
                uint2 bl = *(const uint2*)(sm + sB - base + 8192u + boff);
#pragma unroll
                for (int mt = 0; mt < 2; mt++) {
                    mma16816(acc[mt][nt], ah[mt], (const uint32_t*)&bh);
                    mma16816(acc[mt][nt], ah[mt], (const uint32_t*)&bl);
                    mma16816(acc[mt][nt], al[mt], (const uint32_t*)&bh);
                }
            }
        }

        // dump C frags to padded smem, reset acc
#pragma unroll
        for (int mt = 0; mt < 2; mt++) {
            int r = wid * 32 + mt * 16 + (lane >> 2);
#pragma unroll
            for (int nt = 0; nt < 8; nt++) {
                int col = nt * 8 + (lane & 3) * 2;
                *(float2*)&sCf[r * 66 + col] = make_float2(acc[mt][nt][0], acc[mt][nt][1]);
                *(float2*)&sCf[(r + 8) * 66 + col] = make_float2(acc[mt][nt][2], acc[mt][nt][3]);
                acc[mt][nt][0] = 0.f; acc[mt][nt][1] = 0.f;
                acc[mt][nt][2] = 0.f; acc[mt][nt][3] = 0.f;
            }
        }
        __syncthreads();

        // prefetch B chunk c+2 into buffer (c&1)
        if (c < 10) {
            const uint4* bh = (const uint4*)g_Bfhi + (size_t)(c + 2) * 512;
            const uint4* bl = (const uint4*)g_Bflo + (size_t)(c + 2) * 512;
            uint32_t dst = base + S_B + (uint32_t)(c & 1) * 16384u;
            for (int r = tid; r < 512; r += 128) cpa16(dst + r * 16, bh + r);
            for (int r = tid; r < 512; r += 128) cpa16(dst + 8192u + r * 16, bl + r);
            CP_COMMIT();
        }

        // scalar epilogue: edge = tid
        float t2[4];
#pragma unroll
        for (int o = 0; o < 4; o++) {
            float s = 0.f;
            const float* cb = &sCf[tid * 66 + o * 16];
            const float* bb = &sB2f[(c * 4 + o) * 16];
#pragma unroll
            for (int i = 0; i < 16; i++)
                s = fmaf(cb[i] + bb[i], sTMPf[i * 128 + tid], s);
            t2[o] = s;
        }
#pragma unroll
        for (int q = 0; q < 2; q++) {
            int plane = c * 2 + q;
            float a0 = t2[2 * q], a1 = t2[2 * q + 1];
            float4 o4;
            o4.x = fmaf(a0, p0.x, a1 * p1.x);
            o4.y = fmaf(a0, p0.y, a1 * p1.y);
            o4.z = fmaf(a0, p0.z, a1 * p1.z);
            o4.w = fmaf(a0, p0.w, a1 * p1.w);
            *(float4*)(g_kqv + ((size_t)plane * EN + e) * 4) = o4;
        }
        __syncthreads();
    }
}

// ---------------- Kernel B: per-node attention (warp per node, plane-transposed kqv) --------
__global__ void k_attn(float* __restrict__ out) {
    int warp = threadIdx.x >> 5, lane = threadIdx.x & 31;
    int n = blockIdx.x * 4 + warp;
    int k = lane & 15, rep = lane >> 4;
    int e = n * 16 + k;
    float kk[16], qq[16], vv[16];
#pragma unroll
    for (int r = 0; r < 4; r++) {
        float4 a = *(const float4*)(g_kqv + ((size_t)(4 * rep + r) * EN + e) * 4);
        kk[r*4]=a.x; kk[r*4+1]=a.y; kk[r*4+2]=a.z; kk[r*4+3]=a.w;
        float4 b = *(const float4*)(g_kqv + ((size_t)(8 + 4 * rep + r) * EN + e) * 4);
        qq[r*4]=b.x; qq[r*4+1]=b.y; qq[r*4+2]=b.z; qq[r*4+3]=b.w;
        float4 c = *(const float4*)(g_kqv + ((size_t)(16 + 4 * rep + r) * EN + e) * 4);
        vv[r*4]=c.x; vv[r*4+1]=c.y; vv[r*4+2]=c.z; vv[r*4+3]=c.w;
    }
#pragma unroll
    for (int x = 0; x < 16; x++) {
        float q = qq[x];
        q += __shfl_xor_sync(0xffffffffu, q, 1);
        q += __shfl_xor_sync(0xffffffffu, q, 2);
        q += __shfl_xor_sync(0xffffffffu, q, 4);
        q += __shfl_xor_sync(0xffffffffu, q, 8);
        qq[x] = q;
    }
    const float scale = 0.35355339059327373f * 0.0625f;  // 8^-0.5 * 1/16 (q mean)
    float s0 = 0.f, s1 = 0.f;
#pragma unroll
    for (int x = 0; x < 8; x++) {
        s0 = fmaf(qq[x], kk[x], s0);
        s1 = fmaf(qq[8 + x], kk[8 + x], s1);
    }
    s0 *= scale; s1 *= scale;
    float m0 = s0, m1 = s1;
#pragma unroll
    for (int d = 1; d < 16; d <<= 1) {
        m0 = fmaxf(m0, __shfl_xor_sync(0xffffffffu, m0, d));
        m1 = fmaxf(m1, __shfl_xor_sync(0xffffffffu, m1, d));
    }
    float w0 = __expf(s0 - m0), w1 = __expf(s1 - m1);
    float z0 = w0, z1 = w1;
#pragma unroll
    for (int d = 1; d < 16; d <<= 1) {
        z0 += __shfl_xor_sync(0xffffffffu, z0, d);
        z1 += __shfl_xor_sync(0xffffffffu, z1, d);
    }
    w0 /= z0; w1 /= z1;
    float o[16];
#pragma unroll
    for (int x = 0; x < 8; x++) { o[x] = w0 * vv[x]; o[8 + x] = w1 * vv[8 + x]; }
#pragma unroll
    for (int x = 0; x < 16; x++) {
        float v = o[x];
        v += __shfl_xor_sync(0xffffffffu, v, 1);
        v += __shfl_xor_sync(0xffffffffu, v, 2);
        v += __shfl_xor_sync(0xffffffffu, v, 4);
        v += __shfl_xor_sync(0xffffffffu, v, 8);
        o[x] = v;
    }
    if (k == 0) {
        float* op = out + (size_t)n * 32 + rep * 16;
#pragma unroll
        for (int r = 0; r < 4; r++)
            *(float4*)(op + r * 4) = make_float4(o[r*4], o[r*4+1], o[r*4+2], o[r*4+3]);
    }
}

extern "C" void kernel_launch(void* const* d_in, const int* in_sizes, int n_in,
                              void* d_out, int out_size) {
    const float* basis1 = (const float*)d_in[0];
    const float* basis2 = (const float*)d_in[1];
    const float* ef     = (const float*)d_in[2];
    const float* f      = (const float*)d_in[3];
    const float* W1     = (const float*)d_in[4];
    const float* b1     = (const float*)d_in[5];
    const float* W2     = (const float*)d_in[6];
    const float* b2     = (const float*)d_in[7];
    const int*   nbr    = (const int*)d_in[8];
    float* out = (float*)d_out;

    cudaFuncSetAttribute(k_main, cudaFuncAttributeMaxDynamicSharedMemorySize, SMEM_SZ);

    k_wprep<<<12, 128>>>(W2);
    k_mlp1<<<EN / 32, 128>>>(ef, W1, b1);
    k_tmp<<<EN / 128, 128>>>(basis1, f, nbr);
    k_main<<<EN / 128, 128, SMEM_SZ>>>(b2, basis2);
    k_attn<<<NN / 4, 128>>>(out);
}

// round 4
// speedup vs baseline: 2.2752x; 1.4141x over previous
#include <cuda_runtime.h>
#include <cuda_bf16.h>
#include <cstdint>

#define EN 160000      // edges = N*K
#define NN 10000       // nodes
#define NTILES 1250    // EN/128

// ---------------- static device scratch -----------------------------------------------------
__device__ __align__(16) unsigned char g_Ahi[(size_t)NTILES * 16384]; // h hi: per-128-edge tile, [128 rows x 128B], SW128
__device__ __align__(16) unsigned char g_Alo[(size_t)NTILES * 16384]; // h lo
__device__ __align__(16) uint2 g_Bfhi[12 * 1024];   // W2 hi, m16n8k16 B-fragment layout: [chunk][kt][nt][lane]
__device__ __align__(16) uint2 g_Bflo[12 * 1024];   // W2 lo
__device__ float g_tmpT[NTILES * 16 * 128];         // per tile [i][e_local]
__device__ float g_kqv[(size_t)24 * EN * 4];        // plane-transposed: [m2][edge][dim]

// ---------------- helpers --------------------------------------------------------------------
__device__ __forceinline__ uint32_t smem_u32(const void* p) {
    uint32_t a;
    asm("{ .reg .u64 t; cvta.to.shared.u64 t, %1; cvt.u32.u64 %0, t; }" : "=r"(a) : "l"(p));
    return a;
}
#define SW128(o) ((o) ^ (((o) >> 3) & 0x70))

__device__ __forceinline__ void ldm_x4(uint32_t* r, uint32_t addr) {
    asm volatile("ldmatrix.sync.aligned.m8n8.x4.shared.b16 {%0,%1,%2,%3}, [%4];"
        : "=r"(r[0]), "=r"(r[1]), "=r"(r[2]), "=r"(r[3]) : "r"(addr));
}
__device__ __forceinline__ void mma16816(float* c, const uint32_t* a, const uint32_t* b) {
    asm volatile("mma.sync.aligned.m16n8k16.row.col.f32.bf16.bf16.f32 "
        "{%0,%1,%2,%3}, {%4,%5,%6,%7}, {%8,%9}, {%0,%1,%2,%3};"
        : "+f"(c[0]), "+f"(c[1]), "+f"(c[2]), "+f"(c[3])
        : "r"(a[0]), "r"(a[1]), "r"(a[2]), "r"(a[3]), "r"(b[0]), "r"(b[1]));
}
__device__ __forceinline__ void cpa16(uint32_t dst, const void* src) {
    asm volatile("cp.async.cg.shared.global [%0], [%1], 16;" :: "r"(dst), "l"(src));
}
#define CP_COMMIT() asm volatile("cp.async.commit_group;" ::: "memory")
#define CP_WAIT(n)  asm volatile("cp.async.wait_group %0;" :: "n"(n) : "memory")

__device__ __forceinline__ void split2(float a, float b, uint32_t& h, uint32_t& l) {
    __nv_bfloat16 ah = __float2bfloat16(a), bh = __float2bfloat16(b);
    __nv_bfloat16 al = __float2bfloat16(a - __bfloat162float(ah));
    __nv_bfloat16 bl = __float2bfloat16(b - __bfloat162float(bh));
    h = (uint32_t)__bfloat16_as_ushort(ah) | ((uint32_t)__bfloat16_as_ushort(bh) << 16);
    l = (uint32_t)__bfloat16_as_ushort(al) | ((uint32_t)__bfloat16_as_ushort(bl) << 16);
}

union Pack8 { __nv_bfloat16 b[8]; uint4 u; };

// ---------------- Kernel W: pack W2 into m16n8k16 B-fragment layout, split hi/lo -------------
__global__ void k_wprep(const float* __restrict__ W2) {
    int c = blockIdx.x, tid = threadIdx.x;
    for (int idx = tid; idx < 1024; idx += 128) {
        int kt = idx >> 8, nt = (idx >> 5) & 7, l = idx & 31;
        int row = c * 64 + nt * 8 + (l >> 2);
        int j0 = kt * 16 + (l & 3) * 2;
        const float* wr = W2 + (size_t)row * 64;
        uint32_t h0, l0, h1, l1;
        split2(__ldg(&wr[j0]),     __ldg(&wr[j0 + 1]), h0, l0);
        split2(__ldg(&wr[j0 + 8]), __ldg(&wr[j0 + 9]), h1, l1);
        g_Bfhi[c * 1024 + idx] = make_uint2(h0, h1);
        g_Bflo[c * 1024 + idx] = make_uint2(l0, l1);
    }
}

// ---------------- Kernel 0: h = relu(ef @ W1^T + b1) -> bf16 hi/lo swizzled A tiles ----------
__global__ void k_mlp1(const float* __restrict__ ef, const float* __restrict__ W1,
                       const float* __restrict__ b1) {
    __shared__ float sW1[64 * 33];     // stride 33: bank-conflict-free
    __shared__ float sEF[32 * 33];
    int tid = threadIdx.x;
    int e0 = blockIdx.x * 32;
    for (int r = tid; r < 2048; r += 128) sW1[(r >> 5) * 33 + (r & 31)] = W1[r];
    for (int r = tid; r < 1024; r += 128) sEF[(r >> 5) * 33 + (r & 31)] = ef[e0 * 32 + r];
    __syncthreads();
    int el = tid >> 2;       // local edge 0..31
    int part = tid & 3;      // j-quarter (16 j each)
    float efr[32];
#pragma unroll
    for (int c = 0; c < 32; c++) efr[c] = sEF[el * 33 + c];
    int e = e0 + el;
    int tile = e >> 7, elt = e & 127;
    Pack8 h0, h1, l0, l1;
#pragma unroll
    for (int jj = 0; jj < 16; jj++) {
        int j = part * 16 + jj;
        float acc = __ldg(&b1[j]);
        const float* w = &sW1[j * 33];
#pragma unroll
        for (int c = 0; c < 32; c++) acc = fmaf(efr[c], w[c], acc);
        float x = fmaxf(acc, 0.0f);
        __nv_bfloat16 hb = __float2bfloat16(x);
        __nv_bfloat16 lb = __float2bfloat16(x - __bfloat162float(hb));
        if (jj < 8) { h0.b[jj] = hb; l0.b[jj] = lb; }
        else        { h1.b[jj - 8] = hb; l1.b[jj - 8] = lb; }
    }
    size_t tb = (size_t)tile * 16384;
    uint32_t o0 = elt * 128 + part * 32;
    uint32_t s0 = SW128(o0), s1 = SW128(o0 + 16);
    *(uint4*)(g_Ahi + tb + s0) = h0.u;
    *(uint4*)(g_Ahi + tb + s1) = h1.u;
    *(uint4*)(g_Alo + tb + s0) = l0.u;
    *(uint4*)(g_Alo + tb + s1) = l1.u;
}

// ---------------- Kernel 0b: tmp[e, m*2+l] = sum_d f[src[e],m,d]*basis1[e,d,l] ---------------
__global__ void k_tmp(const float* __restrict__ basis1, const float* __restrict__ f,
                      const int* __restrict__ nbr) {
    int e = blockIdx.x * 128 + threadIdx.x;
    int src = nbr[e];
    const float4* fp = (const float4*)(f + (size_t)src * 32);
    float fr[8][4];
#pragma unroll
    for (int m = 0; m < 8; m++) {
        float4 v = __ldg(&fp[m]);
        fr[m][0] = v.x; fr[m][1] = v.y; fr[m][2] = v.z; fr[m][3] = v.w;
    }
    float4 b0 = __ldg((const float4*)(basis1 + (size_t)e * 8));
    float4 b1v = __ldg((const float4*)(basis1 + (size_t)e * 8 + 4));
    float bd[4][2] = {{b0.x, b0.y}, {b0.z, b0.w}, {b1v.x, b1v.y}, {b1v.z, b1v.w}};
    int tile = e >> 7, elt = e & 127;
    float* dst = g_tmpT + (size_t)tile * (16 * 128) + elt;
#pragma unroll
    for (int m = 0; m < 8; m++)
#pragma unroll
        for (int l = 0; l < 2; l++) {
            float a = fr[m][0] * bd[0][l];
            a = fmaf(fr[m][1], bd[1][l], a);
            a = fmaf(fr[m][2], bd[2][l], a);
            a = fmaf(fr[m][3], bd[3][l], a);
            dst[(m * 2 + l) * 128] = a;
        }
}

// ---------------- Kernel A: HMMA GEMM, A-in-regs, fragment-direct epilogue -------------------
// CTA = 128 edges, 4 warps; warp w owns edges [32w,32w+32). 12 chunks x 64 W2-rows.
// A (hi/lo frags) loaded ONCE into registers. Epilogue contracts fragments directly with tmp
// (i = 8*(nt&1)+2q+{0,1} -> only 4 tmp values/row/thread) + bias, quad-shuffle reduce,
// lane q==0 applies basis2 and stores plane-transposed kqv. No C smem round-trip.
#define S_AHI  0u
#define S_ALO  16384u
#define S_B    32768u          // two 16KB bufs: hi at +0, lo at +8192
#define S_TMP  65536u          // 16 x 128 fp32 (8KB)
#define S_B2   73728u          // 768 fp32 (3KB)
#define SMEM_SZ (76800u + 1024u)

__global__ void __launch_bounds__(128, 2) k_main(const float* __restrict__ b2,
                                                 const float* __restrict__ basis2) {
    extern __shared__ unsigned char smraw[];
    uint32_t base = (smem_u32(smraw) + 1023u) & ~1023u;
    unsigned char* sm = smraw + (base - smem_u32(smraw));
    const float* sTMPf = (const float*)(sm + S_TMP);
    const float* sB2f = (const float*)(sm + S_B2);
    int tid = threadIdx.x, blk = blockIdx.x;
    int wid = tid >> 5, lane = tid & 31;
    int q = lane & 3;

    // ---- prologue: async copies (group0 = A + B0 + tmp + b2; group1 = B1) ----
    {
        const uint4* gA = (const uint4*)(g_Ahi + (size_t)blk * 16384);
        const uint4* gL = (const uint4*)(g_Alo + (size_t)blk * 16384);
        for (int r = tid; r < 1024; r += 128) cpa16(base + S_AHI + r * 16, gA + r);
        for (int r = tid; r < 1024; r += 128) cpa16(base + S_ALO + r * 16, gL + r);
        const uint4* bh = (const uint4*)g_Bfhi;
        const uint4* bl = (const uint4*)g_Bflo;
        for (int r = tid; r < 512; r += 128) cpa16(base + S_B + r * 16, bh + r);
        for (int r = tid; r < 512; r += 128) cpa16(base + S_B + 8192 + r * 16, bl + r);
        const uint4* gt = (const uint4*)(g_tmpT + (size_t)blk * 2048);
        for (int r = tid; r < 512; r += 128) cpa16(base + S_TMP + r * 16, gt + r);
        const uint4* g2 = (const uint4*)b2;
        for (int r = tid; r < 192; r += 128) cpa16(base + S_B2 + r * 16, g2 + r);
        CP_COMMIT();
        for (int r = tid; r < 512; r += 128) cpa16(base + S_B + 16384 + r * 16, bh + 512 + r);
        for (int r = tid; r < 512; r += 128) cpa16(base + S_B + 16384 + 8192 + r * 16, bl + 512 + r);
        CP_COMMIT();
    }

    CP_WAIT(1);               // group0 (A, B0, tmp, b2) complete
    __syncthreads();

    // ---- load A fragments ONCE into registers ----
    uint32_t rowOff = (uint32_t)(wid * 32 + (lane & 7) + 8 * ((lane >> 3) & 1)) * 128u
                    + 16u * (uint32_t)(lane >> 4);
    uint32_t ah[2][4][4], al[2][4][4];
#pragma unroll
    for (int mt = 0; mt < 2; mt++)
#pragma unroll
        for (int kt = 0; kt < 4; kt++) {
            uint32_t so = SW128(rowOff + (uint32_t)mt * 2048u + (uint32_t)kt * 32u);
            ldm_x4(ah[mt][kt], base + S_AHI + so);
            ldm_x4(al[mt][kt], base + S_ALO + so);
        }

    // ---- per-thread tmp values (chunk-invariant): tr[rid][s], i = (s>>1)*8 + 2q + (s&1) ----
    float tr[4][4];
#pragma unroll
    for (int rid = 0; rid < 4; rid++) {
        int row = wid * 32 + (lane >> 2) + rid * 8;
#pragma unroll
        for (int s = 0; s < 4; s++) {
            int i = (s >> 1) * 8 + 2 * q + (s & 1);
            tr[rid][s] = sTMPf[i * 128 + row];
        }
    }

    float acc[2][8][4];
#pragma unroll
    for (int mt = 0; mt < 2; mt++)
#pragma unroll
        for (int nt = 0; nt < 8; nt++)
#pragma unroll
            for (int x = 0; x < 4; x++) acc[mt][nt][x] = 0.0f;

    for (int c = 0; c < 12; c++) {
        if (c < 11) CP_WAIT(1); else CP_WAIT(0);
        __syncthreads();
        const unsigned char* bbuf = sm + S_B + (uint32_t)(c & 1) * 16384u;

#pragma unroll
        for (int kt = 0; kt < 4; kt++) {
#pragma unroll
            for (int nt = 0; nt < 8; nt++) {
                uint32_t boff = (uint32_t)(((kt * 8 + nt) * 32 + lane) * 8);
                uint2 bh = *(const uint2*)(bbuf + boff);
                uint2 bl = *(const uint2*)(bbuf + 8192u + boff);
#pragma unroll
                for (int mt = 0; mt < 2; mt++) {
                    mma16816(acc[mt][nt], ah[mt][kt], (const uint32_t*)&bh);
                    mma16816(acc[mt][nt], ah[mt][kt], (const uint32_t*)&bl);
                    mma16816(acc[mt][nt], al[mt][kt], (const uint32_t*)&bh);
                }
            }
        }
        __syncthreads();      // all warps done reading B buf (c&1)

        if (c < 10) {         // prefetch B chunk c+2 into buffer (c&1)
            const uint4* bh = (const uint4*)g_Bfhi + (size_t)(c + 2) * 512;
            const uint4* bl = (const uint4*)g_Bflo + (size_t)(c + 2) * 512;
            uint32_t dst = base + S_B + (uint32_t)(c & 1) * 16384u;
            for (int r = tid; r < 512; r += 128) cpa16(dst + r * 16, bh + r);
            for (int r = tid; r < 512; r += 128) cpa16(dst + 8192u + r * 16, bl + r);
            CP_COMMIT();
        }

        // ---- fragment-direct epilogue ----
        float p[4][4];        // [rid][o]
#pragma unroll
        for (int rid = 0; rid < 4; rid++)
#pragma unroll
            for (int o = 0; o < 4; o++) p[rid][o] = 0.0f;

#pragma unroll
        for (int mt = 0; mt < 2; mt++)
#pragma unroll
            for (int nt = 0; nt < 8; nt++) {
                int o = nt >> 1, s0 = (nt & 1) * 2;
                float2 bb = *(const float2*)&sB2f[c * 64 + nt * 8 + q * 2];
#pragma unroll
                for (int h = 0; h < 2; h++) {
                    int rid = mt * 2 + h;
                    p[rid][o] = fmaf(acc[mt][nt][h * 2] + bb.x, tr[rid][s0],
                               fmaf(acc[mt][nt][h * 2 + 1] + bb.y, tr[rid][s0 + 1], p[rid][o]));
                    acc[mt][nt][h * 2] = 0.0f;
                    acc[mt][nt][h * 2 + 1] = 0.0f;
                }
            }
        // quad reduction (i-halves 2q,2q+1 across q=0..3 -> full 16-i sum)
#pragma unroll
        for (int rid = 0; rid < 4; rid++)
#pragma unroll
            for (int o = 0; o < 4; o++) {
                p[rid][o] += __shfl_xor_sync(0xffffffffu, p[rid][o], 1);
                p[rid][o] += __shfl_xor_sync(0xffffffffu, p[rid][o], 2);
            }

        if (q == 0) {
#pragma unroll
            for (int rid = 0; rid < 4; rid++) {
                int e = blk * 128 + wid * 32 + (lane >> 2) + rid * 8;
                float4 p0 = __ldg((const float4*)(basis2 + (size_t)e * 8));
                float4 p1 = __ldg((const float4*)(basis2 + (size_t)e * 8 + 4));
#pragma unroll
                for (int pl = 0; pl < 2; pl++) {
                    float a0 = p[rid][pl * 2], a1 = p[rid][pl * 2 + 1];
                    float4 o4;
                    o4.x = fmaf(a0, p0.x, a1 * p1.x);
                    o4.y = fmaf(a0, p0.y, a1 * p1.y);
                    o4.z = fmaf(a0, p0.z, a1 * p1.z);
                    o4.w = fmaf(a0, p0.w, a1 * p1.w);
                    *(float4*)(g_kqv + ((size_t)(c * 2 + pl) * EN + e) * 4) = o4;
                }
            }
        }
    }
}

// ---------------- Kernel B: per-node attention (warp per node, plane-transposed kqv) --------
__global__ void k_attn(float* __restrict__ out) {
    int warp = threadIdx.x >> 5, lane = threadIdx.x & 31;
    int n = blockIdx.x * 4 + warp;
    int k = lane & 15, rep = lane >> 4;
    int e = n * 16 + k;
    float kk[16], qq[16], vv[16];
#pragma unroll
    for (int r = 0; r < 4; r++) {
        float4 a = *(const float4*)(g_kqv + ((size_t)(4 * rep + r) * EN + e) * 4);
        kk[r*4]=a.x; kk[r*4+1]=a.y; kk[r*4+2]=a.z; kk[r*4+3]=a.w;
        float4 b = *(const float4*)(g_kqv + ((size_t)(8 + 4 * rep + r) * EN + e) * 4);
        qq[r*4]=b.x; qq[r*4+1]=b.y; qq[r*4+2]=b.z; qq[r*4+3]=b.w;
        float4 c = *(const float4*)(g_kqv + ((size_t)(16 + 4 * rep + r) * EN + e) * 4);
        vv[r*4]=c.x; vv[r*4+1]=c.y; vv[r*4+2]=c.z; vv[r*4+3]=c.w;
    }
#pragma unroll
    for (int x = 0; x < 16; x++) {
        float qv = qq[x];
        qv += __shfl_xor_sync(0xffffffffu, qv, 1);
        qv += __shfl_xor_sync(0xffffffffu, qv, 2);
        qv += __shfl_xor_sync(0xffffffffu, qv, 4);
        qv += __shfl_xor_sync(0xffffffffu, qv, 8);
        qq[x] = qv;
    }
    const float scale = 0.35355339059327373f * 0.0625f;  // 8^-0.5 * 1/16 (q mean)
    float s0 = 0.f, s1 = 0.f;
#pragma unroll
    for (int x = 0; x < 8; x++) {
        s0 = fmaf(qq[x], kk[x], s0);
        s1 = fmaf(qq[8 + x], kk[8 + x], s1);
    }
    s0 *= scale; s1 *= scale;
    float m0 = s0, m1 = s1;
#pragma unroll
    for (int d = 1; d < 16; d <<= 1) {
        m0 = fmaxf(m0, __shfl_xor_sync(0xffffffffu, m0, d));
        m1 = fmaxf(m1, __shfl_xor_sync(0xffffffffu, m1, d));
    }
    float w0 = __expf(s0 - m0), w1 = __expf(s1 - m1);
    float z0 = w0, z1 = w1;
#pragma unroll
    for (int d = 1; d < 16; d <<= 1) {
        z0 += __shfl_xor_sync(0xffffffffu, z0, d);
        z1 += __shfl_xor_sync(0xffffffffu, z1, d);
    }
    w0 /= z0; w1 /= z1;
    float o[16];
#pragma unroll
    for (int x = 0; x < 8; x++) { o[x] = w0 * vv[x]; o[8 + x] = w1 * vv[8 + x]; }
#pragma unroll
    for (int x = 0; x < 16; x++) {
        float v = o[x];
        v += __shfl_xor_sync(0xffffffffu, v, 1);
        v += __shfl_xor_sync(0xffffffffu, v, 2);
        v += __shfl_xor_sync(0xffffffffu, v, 4);
        v += __shfl_xor_sync(0xffffffffu, v, 8);
        o[x] = v;
    }
    if (k == 0) {
        float* op = out + (size_t)n * 32 + rep * 16;
#pragma unroll
        for (int r = 0; r < 4; r++)
            *(float4*)(op + r * 4) = make_float4(o[r*4], o[r*4+1], o[r*4+2], o[r*4+3]);
    }
}

extern "C" void kernel_launch(void* const* d_in, const int* in_sizes, int n_in,
                              void* d_out, int out_size) {
    const float* basis1 = (const float*)d_in[0];
    const float* basis2 = (const float*)d_in[1];
    const float* ef     = (const float*)d_in[2];
    const float* f      = (const float*)d_in[3];
    const float* W1     = (const float*)d_in[4];
    const float* b1     = (const float*)d_in[5];
    const float* W2     = (const float*)d_in[6];
    const float* b2     = (const float*)d_in[7];
    const int*   nbr    = (const int*)d_in[8];
    float* out = (float*)d_out;

    cudaFuncSetAttribute(k_main, cudaFuncAttributeMaxDynamicSharedMemorySize, SMEM_SZ);

    k_wprep<<<12, 128>>>(W2);
    k_mlp1<<<EN / 32, 128>>>(ef, W1, b1);
    k_tmp<<<EN / 128, 128>>>(basis1, f, nbr);
    k_main<<<EN / 128, 128, SMEM_SZ>>>(b2, basis2);
    k_attn<<<NN / 4, 128>>>(out);
}

// round 5
// speedup vs baseline: 2.4613x; 1.0818x over previous
#include <cuda_runtime.h>
#include <cuda_bf16.h>
#include <cstdint>

#define EN 160000      // edges = N*K
#define NN 10000       // nodes
#define NTILES 1250    // EN/128

// ---------------- static device scratch -----------------------------------------------------
__device__ __align__(16) unsigned char g_Ahi[(size_t)NTILES * 16384]; // h hi: per-128-edge tile, SW128
__device__ __align__(16) unsigned char g_Alo[(size_t)NTILES * 16384]; // h lo
__device__ __align__(16) uint2 g_Bfhi[12 * 1024];   // W2 hi, m16n8k16 B-frag layout [chunk][kt][nt][lane]
__device__ __align__(16) uint2 g_Bflo[12 * 1024];   // W2 lo

// ---------------- helpers --------------------------------------------------------------------
__device__ __forceinline__ uint32_t smem_u32(const void* p) {
    uint32_t a;
    asm("{ .reg .u64 t; cvta.to.shared.u64 t, %1; cvt.u32.u64 %0, t; }" : "=r"(a) : "l"(p));
    return a;
}
#define SW128(o) ((o) ^ (((o) >> 3) & 0x70))

__device__ __forceinline__ void ldm_x4(uint32_t* r, uint32_t addr) {
    asm volatile("ldmatrix.sync.aligned.m8n8.x4.shared.b16 {%0,%1,%2,%3}, [%4];"
        : "=r"(r[0]), "=r"(r[1]), "=r"(r[2]), "=r"(r[3]) : "r"(addr));
}
__device__ __forceinline__ void mma16816(float* c, const uint32_t* a, const uint32_t* b) {
    asm volatile("mma.sync.aligned.m16n8k16.row.col.f32.bf16.bf16.f32 "
        "{%0,%1,%2,%3}, {%4,%5,%6,%7}, {%8,%9}, {%0,%1,%2,%3};"
        : "+f"(c[0]), "+f"(c[1]), "+f"(c[2]), "+f"(c[3])
        : "r"(a[0]), "r"(a[1]), "r"(a[2]), "r"(a[3]), "r"(b[0]), "r"(b[1]));
}
__device__ __forceinline__ void cpa16(uint32_t dst, const void* src) {
    asm volatile("cp.async.cg.shared.global [%0], [%1], 16;" :: "r"(dst), "l"(src));
}
#define CP_COMMIT() asm volatile("cp.async.commit_group;" ::: "memory")
#define CP_WAIT(n)  asm volatile("cp.async.wait_group %0;" :: "n"(n) : "memory")

__device__ __forceinline__ void split2(float a, float b, uint32_t& h, uint32_t& l) {
    __nv_bfloat16 ah = __float2bfloat16(a), bh = __float2bfloat16(b);
    __nv_bfloat16 al = __float2bfloat16(a - __bfloat162float(ah));
    __nv_bfloat16 bl = __float2bfloat16(b - __bfloat162float(bh));
    h = (uint32_t)__bfloat16_as_ushort(ah) | ((uint32_t)__bfloat16_as_ushort(bh) << 16);
    l = (uint32_t)__bfloat16_as_ushort(al) | ((uint32_t)__bfloat16_as_ushort(bl) << 16);
}

union Pack8 { __nv_bfloat16 b[8]; uint4 u; };

// ---------------- Kernel W: pack W2 into m16n8k16 B-fragment layout, split hi/lo -------------
__global__ void k_wprep(const float* __restrict__ W2) {
    int c = blockIdx.x, tid = threadIdx.x;
    for (int idx = tid; idx < 1024; idx += 128) {
        int kt = idx >> 8, nt = (idx >> 5) & 7, l = idx & 31;
        int row = c * 64 + nt * 8 + (l >> 2);
        int j0 = kt * 16 + (l & 3) * 2;
        const float* wr = W2 + (size_t)row * 64;
        uint32_t h0, l0, h1, l1;
        split2(__ldg(&wr[j0]),     __ldg(&wr[j0 + 1]), h0, l0);
        split2(__ldg(&wr[j0 + 8]), __ldg(&wr[j0 + 9]), h1, l1);
        g_Bfhi[c * 1024 + idx] = make_uint2(h0, h1);
        g_Bflo[c * 1024 + idx] = make_uint2(l0, l1);
    }
}

// ---------------- Kernel 0: h = relu(ef @ W1^T + b1) -> bf16 hi/lo swizzled A tiles ----------
__global__ void k_mlp1(const float* __restrict__ ef, const float* __restrict__ W1,
                       const float* __restrict__ b1) {
    __shared__ float sW1[64 * 33];
    __shared__ float sEF[32 * 33];
    int tid = threadIdx.x;
    int e0 = blockIdx.x * 32;
    for (int r = tid; r < 2048; r += 128) sW1[(r >> 5) * 33 + (r & 31)] = W1[r];
    for (int r = tid; r < 1024; r += 128) sEF[(r >> 5) * 33 + (r & 31)] = ef[e0 * 32 + r];
    __syncthreads();
    int el = tid >> 2;
    int part = tid & 3;
    float efr[32];
#pragma unroll
    for (int c = 0; c < 32; c++) efr[c] = sEF[el * 33 + c];
    int e = e0 + el;
    int tile = e >> 7, elt = e & 127;
    Pack8 h0, h1, l0, l1;
#pragma unroll
    for (int jj = 0; jj < 16; jj++) {
        int j = part * 16 + jj;
        float acc = __ldg(&b1[j]);
        const float* w = &sW1[j * 33];
#pragma unroll
        for (int c = 0; c < 32; c++) acc = fmaf(efr[c], w[c], acc);
        float x = fmaxf(acc, 0.0f);
        __nv_bfloat16 hb = __float2bfloat16(x);
        __nv_bfloat16 lb = __float2bfloat16(x - __bfloat162float(hb));
        if (jj < 8) { h0.b[jj] = hb; l0.b[jj] = lb; }
        else        { h1.b[jj - 8] = hb; l1.b[jj - 8] = lb; }
    }
    size_t tb = (size_t)tile * 16384;
    uint32_t o0 = elt * 128 + part * 32;
    uint32_t s0 = SW128(o0), s1 = SW128(o0 + 16);
    *(uint4*)(g_Ahi + tb + s0) = h0.u;
    *(uint4*)(g_Ahi + tb + s1) = h1.u;
    *(uint4*)(g_Alo + tb + s0) = l0.u;
    *(uint4*)(g_Alo + tb + s1) = l1.u;
}

// ---------------- Kernel A: HMMA GEMM + tmp + epilogue + in-CTA attention --------------------
// CTA = 128 edges = 8 nodes. Smem region R0 is A/tmp during prologue, then kqv k/v planes +
// q-node accumulators during the loop. 3-buffer B pipeline, ONE sync per chunk.
#define S_AHI  0u              // prologue only
#define S_ALO  16384u          // prologue only
#define S_TMP  32768u          // prologue only (..40960)
#define S_KQV  0u              // loop: 16 planes x 128 edges x 16B = 32768
#define S_QN   32768u          // loop: 8 nodes x 8 qplanes x 16B = 1024
#define S_B    40960u          // 3 bufs x 16384: hi +0, lo +8192  (..90112)
#define S_B2   90112u          // 768 f  (..93184)
#define S_BAS  93184u          // basis2 tile: 128 x 32B = 4096 (..97280)
#define SMEM_SZ (97280u + 1024u)

__global__ void __launch_bounds__(128, 2) k_main(const float* __restrict__ b2,
                                                 const float* __restrict__ basis2,
                                                 const float* __restrict__ basis1,
                                                 const float* __restrict__ f,
                                                 const int* __restrict__ nbr,
                                                 float* __restrict__ out) {
    extern __shared__ unsigned char smraw[];
    uint32_t base = (smem_u32(smraw) + 1023u) & ~1023u;
    unsigned char* sm = smraw + (base - smem_u32(smraw));
    const float* sB2f = (const float*)(sm + S_B2);
    int tid = threadIdx.x, blk = blockIdx.x;
    int wid = tid >> 5, lane = tid & 31;
    int q = lane & 3;

    // ---- prologue: async copies. G0 = A + B0 + b2 + basis2; G1 = B1; G2 = B2 ----
    {
        const uint4* gA = (const uint4*)(g_Ahi + (size_t)blk * 16384);
        const uint4* gL = (const uint4*)(g_Alo + (size_t)blk * 16384);
        for (int r = tid; r < 1024; r += 128) cpa16(base + S_AHI + r * 16, gA + r);
        for (int r = tid; r < 1024; r += 128) cpa16(base + S_ALO + r * 16, gL + r);
        const uint4* bh = (const uint4*)g_Bfhi;
        const uint4* bl = (const uint4*)g_Bflo;
        for (int r = tid; r < 512; r += 128) cpa16(base + S_B + r * 16, bh + r);
        for (int r = tid; r < 512; r += 128) cpa16(base + S_B + 8192 + r * 16, bl + r);
        const uint4* g2 = (const uint4*)b2;
        for (int r = tid; r < 192; r += 128) cpa16(base + S_B2 + r * 16, g2 + r);
        const uint4* gb = (const uint4*)(basis2 + (size_t)blk * 1024);
        for (int r = tid; r < 256; r += 128) cpa16(base + S_BAS + r * 16, gb + r);
        CP_COMMIT();                                             // G0
        for (int r = tid; r < 512; r += 128) cpa16(base + S_B + 16384 + r * 16, bh + 512 + r);
        for (int r = tid; r < 512; r += 128) cpa16(base + S_B + 16384 + 8192 + r * 16, bl + 512 + r);
        CP_COMMIT();                                             // G1
        for (int r = tid; r < 512; r += 128) cpa16(base + S_B + 32768 + r * 16, bh + 1024 + r);
        for (int r = tid; r < 512; r += 128) cpa16(base + S_B + 32768 + 8192 + r * 16, bl + 1024 + r);
        CP_COMMIT();                                             // G2
    }

    // ---- fused k_tmp: tmp[e, m*2+l] = sum_d f[src,m,d]*basis1[e,d,l] (overlaps cp.async) ----
    {
        int e = blk * 128 + tid;
        int src = __ldg(&nbr[e]);
        const float4* fp = (const float4*)(f + (size_t)src * 32);
        float fr[8][4];
#pragma unroll
        for (int m = 0; m < 8; m++) {
            float4 v = __ldg(&fp[m]);
            fr[m][0] = v.x; fr[m][1] = v.y; fr[m][2] = v.z; fr[m][3] = v.w;
        }
        float4 b0 = __ldg((const float4*)(basis1 + (size_t)e * 8));
        float4 b1v = __ldg((const float4*)(basis1 + (size_t)e * 8 + 4));
        float bd[4][2] = {{b0.x, b0.y}, {b0.z, b0.w}, {b1v.x, b1v.y}, {b1v.z, b1v.w}};
        float* dst = (float*)(sm + S_TMP);
#pragma unroll
        for (int m = 0; m < 8; m++)
#pragma unroll
            for (int l = 0; l < 2; l++) {
                float a = fr[m][0] * bd[0][l];
                a = fmaf(fr[m][1], bd[1][l], a);
                a = fmaf(fr[m][2], bd[2][l], a);
                a = fmaf(fr[m][3], bd[3][l], a);
                dst[(m * 2 + l) * 128 + tid] = a;
            }
    }

    CP_WAIT(2);               // G0 (A, B0, b2, basis2) complete
    __syncthreads();          // cross-thread visibility of G0 + tmp stores

    // ---- A fragments once into registers ----
    uint32_t rowOff = (uint32_t)(wid * 32 + (lane & 7) + 8 * ((lane >> 3) & 1)) * 128u
                    + 16u * (uint32_t)(lane >> 4);
    uint32_t ah[2][4][4], al[2][4][4];
#pragma unroll
    for (int mt = 0; mt < 2; mt++)
#pragma unroll
        for (int kt = 0; kt < 4; kt++) {
            uint32_t so = SW128(rowOff + (uint32_t)mt * 2048u + (uint32_t)kt * 32u);
            ldm_x4(ah[mt][kt], base + S_AHI + so);
            ldm_x4(al[mt][kt], base + S_ALO + so);
        }

    // ---- chunk-invariant tmp values: tr[rid][s], i = (s>>1)*8 + 2q + (s&1) ----
    float tr[4][4];
    {
        const float* sTMPf = (const float*)(sm + S_TMP);
#pragma unroll
        for (int rid = 0; rid < 4; rid++) {
            int row = wid * 32 + (lane >> 2) + rid * 8;
#pragma unroll
            for (int s = 0; s < 4; s++) {
                int i = (s >> 1) * 8 + 2 * q + (s & 1);
                tr[rid][s] = sTMPf[i * 128 + row];
            }
        }
    }

    float acc[2][8][4];
#pragma unroll
    for (int mt = 0; mt < 2; mt++)
#pragma unroll
        for (int nt = 0; nt < 8; nt++)
#pragma unroll
            for (int x = 0; x < 4; x++) acc[mt][nt][x] = 0.0f;

    for (int c = 0; c < 12; c++) {
        // wait for B(c); c=0 already ensured in prologue
        if (c == 0) { CP_WAIT(2); }
        else if (c <= 10) { CP_WAIT(1); }
        else { CP_WAIT(0); }
        __syncthreads();      // visibility of B(c) to all warps; all warps done with c-1

        if (c >= 1 && c <= 9) {   // prefetch B(c+2) into buf (c+2)%3 (last used by chunk c-1)
            int bufi = (c + 2) % 3;
            const uint4* bh = (const uint4*)g_Bfhi + (size_t)(c + 2) * 512;
            const uint4* bl = (const uint4*)g_Bflo + (size_t)(c + 2) * 512;
            uint32_t dst = base + S_B + (uint32_t)bufi * 16384u;
            for (int r = tid; r < 512; r += 128) cpa16(dst + r * 16, bh + r);
            for (int r = tid; r < 512; r += 128) cpa16(dst + 8192u + r * 16, bl + r);
            CP_COMMIT();
        }

        const unsigned char* bbuf = sm + S_B + (uint32_t)(c % 3) * 16384u;
#pragma unroll
        for (int kt = 0; kt < 4; kt++) {
#pragma unroll
            for (int nt = 0; nt < 8; nt++) {
                uint32_t boff = (uint32_t)(((kt * 8 + nt) * 32 + lane) * 8);
                uint2 bh = *(const uint2*)(bbuf + boff);
                uint2 bl = *(const uint2*)(bbuf + 8192u + boff);
#pragma unroll
                for (int mt = 0; mt < 2; mt++) {
                    mma16816(acc[mt][nt], ah[mt][kt], (const uint32_t*)&bh);
                    mma16816(acc[mt][nt], ah[mt][kt], (const uint32_t*)&bl);
                    mma16816(acc[mt][nt], al[mt][kt], (const uint32_t*)&bh);
                }
            }
        }

        // ---- fragment-direct epilogue: p[rid][o] = sum_i (C+b2)*tmp ----
        float p[4][4];
#pragma unroll
        for (int rid = 0; rid < 4; rid++)
#pragma unroll
            for (int o = 0; o < 4; o++) p[rid][o] = 0.0f;
#pragma unroll
        for (int mt = 0; mt < 2; mt++)
#pragma unroll
            for (int nt = 0; nt < 8; nt++) {
                int o = nt >> 1, s0 = (nt & 1) * 2;
                float2 bb = *(const float2*)&sB2f[c * 64 + nt * 8 + q * 2];
#pragma unroll
                for (int h = 0; h < 2; h++) {
                    int rid = mt * 2 + h;
                    p[rid][o] = fmaf(acc[mt][nt][h * 2] + bb.x, tr[rid][s0],
                               fmaf(acc[mt][nt][h * 2 + 1] + bb.y, tr[rid][s0 + 1], p[rid][o]));
                    acc[mt][nt][h * 2] = 0.0f;
                    acc[mt][nt][h * 2 + 1] = 0.0f;
                }
            }
#pragma unroll
        for (int rid = 0; rid < 4; rid++)
#pragma unroll
            for (int o = 0; o < 4; o++) {
                p[rid][o] += __shfl_xor_sync(0xffffffffu, p[rid][o], 1);
                p[rid][o] += __shfl_xor_sync(0xffffffffu, p[rid][o], 2);
            }

        if (c < 4 || c >= 8) {
            // k planes (c<4 -> smem planes 0..7) / v planes (c>=8 -> smem planes 8..15)
            if (q == 0) {
                int psm0 = (c < 4) ? (c * 2) : ((c - 8) * 2 + 8);
#pragma unroll
                for (int rid = 0; rid < 4; rid++) {
                    int el = wid * 32 + (lane >> 2) + rid * 8;
                    float4 p0 = *(const float4*)(sm + S_BAS + el * 32);
                    float4 p1 = *(const float4*)(sm + S_BAS + el * 32 + 16);
#pragma unroll
                    for (int pl = 0; pl < 2; pl++) {
                        float a0 = p[rid][pl * 2], a1 = p[rid][pl * 2 + 1];
                        float4 o4;
                        o4.x = fmaf(a0, p0.x, a1 * p1.x);
                        o4.y = fmaf(a0, p0.y, a1 * p1.y);
                        o4.z = fmaf(a0, p0.z, a1 * p1.z);
                        o4.w = fmaf(a0, p0.w, a1 * p1.w);
                        *(float4*)(sm + S_KQV + (size_t)(psm0 + pl) * 2048 + el * 16) = o4;
                    }
                }
            }
        } else {
            // q chunks: per-node sum over 16 edges via warp shuffles (warp owns 2 nodes)
            int qp0 = (c - 4) * 2;
            float4 an[2][2];   // [pl][node 0/1]
#pragma unroll
            for (int pl = 0; pl < 2; pl++)
#pragma unroll
                for (int nn = 0; nn < 2; nn++) an[pl][nn] = make_float4(0.f, 0.f, 0.f, 0.f);
#pragma unroll
            for (int rid = 0; rid < 4; rid++) {
                int el = wid * 32 + (lane >> 2) + rid * 8;
                float4 p0 = *(const float4*)(sm + S_BAS + el * 32);
                float4 p1 = *(const float4*)(sm + S_BAS + el * 32 + 16);
                int nn = rid >> 1;
#pragma unroll
                for (int pl = 0; pl < 2; pl++) {
                    float a0 = p[rid][pl * 2], a1 = p[rid][pl * 2 + 1];
                    an[pl][nn].x = fmaf(a0, p0.x, fmaf(a1, p1.x, an[pl][nn].x));
                    an[pl][nn].y = fmaf(a0, p0.y, fmaf(a1, p1.y, an[pl][nn].y));
                    an[pl][nn].z = fmaf(a0, p0.z, fmaf(a1, p1.z, an[pl][nn].z));
                    an[pl][nn].w = fmaf(a0, p0.w, fmaf(a1, p1.w, an[pl][nn].w));
                }
            }
#pragma unroll
            for (int pl = 0; pl < 2; pl++)
#pragma unroll
                for (int nn = 0; nn < 2; nn++) {
#pragma unroll
                    for (int d = 4; d <= 16; d <<= 1) {
                        an[pl][nn].x += __shfl_xor_sync(0xffffffffu, an[pl][nn].x, d);
                        an[pl][nn].y += __shfl_xor_sync(0xffffffffu, an[pl][nn].y, d);
                        an[pl][nn].z += __shfl_xor_sync(0xffffffffu, an[pl][nn].z, d);
                        an[pl][nn].w += __shfl_xor_sync(0xffffffffu, an[pl][nn].w, d);
                    }
                }
            if (lane == 0) {
#pragma unroll
                for (int pl = 0; pl < 2; pl++)
#pragma unroll
                    for (int nn = 0; nn < 2; nn++)
                        *(float4*)(sm + S_QN + (size_t)((wid * 2 + nn) * 8 + qp0 + pl) * 16)
                            = an[pl][nn];
            }
        }
    }

    // ---- in-CTA attention: 8 nodes, 16 lanes per node ----
    __syncthreads();
    {
        int k16 = lane & 15, nh = lane >> 4;
        int nl = wid * 2 + nh;
        int n = blk * 8 + nl;
        int el = nl * 16 + k16;
        float kk[32], vv[32], qn[32];
#pragma unroll
        for (int pp = 0; pp < 8; pp++) {
            float4 a = *(const float4*)(sm + S_KQV + (size_t)pp * 2048 + el * 16);
            kk[pp*4]=a.x; kk[pp*4+1]=a.y; kk[pp*4+2]=a.z; kk[pp*4+3]=a.w;
            float4 v = *(const float4*)(sm + S_KQV + (size_t)(8 + pp) * 2048 + el * 16);
            vv[pp*4]=v.x; vv[pp*4+1]=v.y; vv[pp*4+2]=v.z; vv[pp*4+3]=v.w;
            float4 qv = *(const float4*)(sm + S_QN + (size_t)(nl * 8 + pp) * 16);
            qn[pp*4]=qv.x; qn[pp*4+1]=qv.y; qn[pp*4+2]=qv.z; qn[pp*4+3]=qv.w;
        }
        const float scale = 0.35355339059327373f * 0.0625f;  // 8^-0.5 * 1/16 (q mean)
        float s[4];
#pragma unroll
        for (int h = 0; h < 4; h++) {
            float a = 0.f;
#pragma unroll
            for (int x = 0; x < 8; x++) a = fmaf(qn[h * 8 + x], kk[h * 8 + x], a);
            s[h] = a * scale;
        }
#pragma unroll
        for (int h = 0; h < 4; h++) {
            float m = s[h];
#pragma unroll
            for (int d = 1; d < 16; d <<= 1)
                m = fmaxf(m, __shfl_xor_sync(0xffffffffu, m, d));
            float w = __expf(s[h] - m);
            float z = w;
#pragma unroll
            for (int d = 1; d < 16; d <<= 1)
                z += __shfl_xor_sync(0xffffffffu, z, d);
            s[h] = w / z;
        }
        float o[32];
#pragma unroll
        for (int x = 0; x < 32; x++) {
            float v = s[x >> 3] * vv[x];
            v += __shfl_xor_sync(0xffffffffu, v, 1);
            v += __shfl_xor_sync(0xffffffffu, v, 2);
            v += __shfl_xor_sync(0xffffffffu, v, 4);
            v += __shfl_xor_sync(0xffffffffu, v, 8);
            o[x] = v;
        }
        if (k16 == 0) {
            float* op = out + (size_t)n * 32;
#pragma unroll
            for (int r = 0; r < 8; r++)
                *(float4*)(op + r * 4) = make_float4(o[r*4], o[r*4+1], o[r*4+2], o[r*4+3]);
        }
    }
}

extern "C" void kernel_launch(void* const* d_in, const int* in_sizes, int n_in,
                              void* d_out, int out_size) {
    const float* basis1 = (const float*)d_in[0];
    const float* basis2 = (const float*)d_in[1];
    const float* ef     = (const float*)d_in[2];
    const float* f      = (const float*)d_in[3];
    const float* W1     = (const float*)d_in[4];
    const float* b1     = (const float*)d_in[5];
    const float* W2     = (const float*)d_in[6];
    const float* b2     = (const float*)d_in[7];
    const int*   nbr    = (const int*)d_in[8];
    float* out = (float*)d_out;

    cudaFuncSetAttribute(k_main, cudaFuncAttributeMaxDynamicSharedMemorySize, SMEM_SZ);

    k_wprep<<<12, 128>>>(W2);
    k_mlp1<<<EN / 32, 128>>>(ef, W1, b1);
    k_main<<<EN / 128, 128, SMEM_SZ>>>(b2, basis2, basis1, f, nbr, out);
}

// round 7
// speedup vs baseline: 3.0702x; 1.2474x over previous
#include <cuda_runtime.h>
#include <cuda_bf16.h>
#include <cstdint>

#define EN 160000      // edges = N*K
#define NN 10000       // nodes

// ---------------- static device scratch -----------------------------------------------------
// A (h) in m16n8k16 fragment layout, split bf16 hi/lo.
// Per warp-block (32 edges): 512 uint4 = [hl][mt][kt][lane]; 5000 warp-blocks.
__device__ __align__(16) uint4 g_Af[(size_t)5000 * 512];
__device__ __align__(16) uint2 g_Bfhi[12 * 1024];   // W2 hi, m16n8k16 B-frag layout [chunk][kt][nt][lane]
__device__ __align__(16) uint2 g_Bflo[12 * 1024];   // W2 lo

// ---------------- helpers --------------------------------------------------------------------
__device__ __forceinline__ uint32_t smem_u32(const void* p) {
    uint32_t a;
    asm("{ .reg .u64 t; cvta.to.shared.u64 t, %1; cvt.u32.u64 %0, t; }" : "=r"(a) : "l"(p));
    return a;
}
__device__ __forceinline__ void mma16816(float* c, const uint32_t* a, const uint32_t* b) {
    asm volatile("mma.sync.aligned.m16n8k16.row.col.f32.bf16.bf16.f32 "
        "{%0,%1,%2,%3}, {%4,%5,%6,%7}, {%8,%9}, {%0,%1,%2,%3};"
        : "+f"(c[0]), "+f"(c[1]), "+f"(c[2]), "+f"(c[3])
        : "r"(a[0]), "r"(a[1]), "r"(a[2]), "r"(a[3]), "r"(b[0]), "r"(b[1]));
}
__device__ __forceinline__ void cpa16(uint32_t dst, const void* src) {
    asm volatile("cp.async.cg.shared.global [%0], [%1], 16;" :: "r"(dst), "l"(src));
}
#define CP_COMMIT() asm volatile("cp.async.commit_group;" ::: "memory")
#define CP_WAIT(n)  asm volatile("cp.async.wait_group %0;" :: "n"(n) : "memory")

__device__ __forceinline__ void split2(float a, float b, uint32_t& h, uint32_t& l) {
    __nv_bfloat16 ah = __float2bfloat16(a), bh = __float2bfloat16(b);
    __nv_bfloat16 al = __float2bfloat16(a - __bfloat162float(ah));
    __nv_bfloat16 bl = __float2bfloat16(b - __bfloat162float(bh));
    h = (uint32_t)__bfloat16_as_ushort(ah) | ((uint32_t)__bfloat16_as_ushort(bh) << 16);
    l = (uint32_t)__bfloat16_as_ushort(al) | ((uint32_t)__bfloat16_as_ushort(bl) << 16);
}

// ---------------- Kernel 0: h = relu(ef @ W1^T + b1) -> A frag layout (+ fused W2 prep) ------
// Block = 32 edges = one consuming warp's A tile. Conflict-free float4 W1 reads
// (p-rotated slot layout). Phase 2 packs m16n8k16 fragments and stores coalesced.
__global__ void __launch_bounds__(128) k_mlp1(const float* __restrict__ ef,
                                              const float* __restrict__ W1,
                                              const float* __restrict__ b1,
                                              const float* __restrict__ W2) {
    __shared__ float sW[2048];       // [jj][p][slot(c4 rot p)][4]
    __shared__ float sEF[32 * 36];   // stride 36: aligned float4, conflict-free
    __shared__ float sH[32 * 72];    // h fp32, stride 72
    int tid = threadIdx.x, bid = blockIdx.x;
    int e0 = bid * 32;

    for (int r = tid; r < 2048; r += 128) {
        int j = r >> 5, c = r & 31;
        int p = j >> 4, jj = j & 15, c4 = c >> 2, ci = c & 3;
        sW[((jj * 4 + p) * 8 + ((c4 + p) & 7)) * 4 + ci] = W1[r];
    }
    for (int r = tid; r < 1024; r += 128) sEF[(r >> 5) * 36 + (r & 31)] = ef[e0 * 32 + r];
    __syncthreads();

    int el = tid >> 2, p = tid & 3;
    float4 efv[8];
#pragma unroll
    for (int c4 = 0; c4 < 8; c4++) efv[c4] = *(const float4*)&sEF[el * 36 + c4 * 4];
    float hv[16];
#pragma unroll
    for (int jj = 0; jj < 16; jj++) {
        float acc = __ldg(&b1[p * 16 + jj]);
#pragma unroll
        for (int c4 = 0; c4 < 8; c4++) {
            float4 wv = *(const float4*)&sW[((jj * 4 + p) * 8 + ((c4 + p) & 7)) * 4];
            acc = fmaf(efv[c4].x, wv.x, acc);
            acc = fmaf(efv[c4].y, wv.y, acc);
            acc = fmaf(efv[c4].z, wv.z, acc);
            acc = fmaf(efv[c4].w, wv.w, acc);
        }
        hv[jj] = fmaxf(acc, 0.0f);
    }
#pragma unroll
    for (int j4 = 0; j4 < 4; j4++)
        *(float4*)&sH[el * 72 + p * 16 + j4 * 4] =
            make_float4(hv[j4 * 4], hv[j4 * 4 + 1], hv[j4 * 4 + 2], hv[j4 * 4 + 3]);
    __syncthreads();

    // phase 2: pack A fragments. Per warp-block: 512 uint4 = [hl][mt][kt][lane].
    uint4* gA = g_Af + (size_t)bid * 512;
#pragma unroll
    for (int it = 0; it < 2; it++) {
        int mt = it, kt = (tid >> 5) & 3, ln = tid & 31;
        int r0 = mt * 16 + (ln >> 2);
        int c0 = kt * 16 + 2 * (ln & 3);
        float2 v0 = *(const float2*)&sH[r0 * 72 + c0];
        float2 v1 = *(const float2*)&sH[(r0 + 8) * 72 + c0];
        float2 v2 = *(const float2*)&sH[r0 * 72 + c0 + 8];
        float2 v3 = *(const float2*)&sH[(r0 + 8) * 72 + c0 + 8];
        uint4 hi, lo;
        split2(v0.x, v0.y, hi.x, lo.x);
        split2(v1.x, v1.y, hi.y, lo.y);
        split2(v2.x, v2.y, hi.z, lo.z);
        split2(v3.x, v3.y, hi.w, lo.w);
        gA[(size_t)((0 * 2 + mt) * 4 + kt) * 32 + ln] = hi;
        gA[(size_t)((1 * 2 + mt) * 4 + kt) * 32 + ln] = lo;
    }

    // fused W2 prep (blocks 0..11, one chunk each)
    if (bid < 12) {
        int c = bid;
        for (int idx = tid; idx < 1024; idx += 128) {
            int kt = idx >> 8, nt = (idx >> 5) & 7, l = idx & 31;
            int row = c * 64 + nt * 8 + (l >> 2);
            int j0 = kt * 16 + (l & 3) * 2;
            const float* wr = W2 + (size_t)row * 64;
            uint32_t h0, l0, h1, l1;
            split2(__ldg(&wr[j0]),     __ldg(&wr[j0 + 1]), h0, l0);
            split2(__ldg(&wr[j0 + 8]), __ldg(&wr[j0 + 9]), h1, l1);
            g_Bfhi[c * 1024 + idx] = make_uint2(h0, h1);
            g_Bflo[c * 1024 + idx] = make_uint2(l0, l1);
        }
    }
}

// ---------------- Kernel A: HMMA GEMM + tmp + epilogue + in-CTA attention --------------------
// CTA = 128 edges = 8 nodes. A frags via direct LDG (no smem stage). Chunk-PAIR iterations:
// 2x32KB B buffers, one __syncthreads per pair (6 total).
#define S_KQV  0u              // 16 planes x 128 x 16B = 32768 (aliased: tmp 8K in prologue)
#define S_TMP  0u
#define S_QN   32768u          // 1024
#define S_B    33792u          // 2 pair-bufs x 32768; within pair: sc*16384, hi +0, lo +8192
#define S_B2   99328u          // 3072
#define S_BAS  102400u         // 4096
#define SMEM_SZ (106496u + 1024u)

__global__ void __launch_bounds__(128, 2) k_main(const float* __restrict__ b2,
                                                 const float* __restrict__ basis2,
                                                 const float* __restrict__ basis1,
                                                 const float* __restrict__ f,
                                                 const int* __restrict__ nbr,
                                                 float* __restrict__ out) {
    extern __shared__ unsigned char smraw[];
    uint32_t base = (smem_u32(smraw) + 1023u) & ~1023u;
    unsigned char* sm = smraw + (base - smem_u32(smraw));
    const float* sB2f = (const float*)(sm + S_B2);
    int tid = threadIdx.x, blk = blockIdx.x;
    int wid = tid >> 5, lane = tid & 31;
    int q = lane & 3;

    // ---- prologue: cp.async G0 = B pair0 + b2 + basis2 ----
    {
        const uint4* bh = (const uint4*)g_Bfhi;
        const uint4* bl = (const uint4*)g_Bflo;
#pragma unroll
        for (int sc = 0; sc < 2; sc++) {
            for (int r = tid; r < 512; r += 128)
                cpa16(base + S_B + sc * 16384u + r * 16, bh + (size_t)sc * 512 + r);
            for (int r = tid; r < 512; r += 128)
                cpa16(base + S_B + sc * 16384u + 8192u + r * 16, bl + (size_t)sc * 512 + r);
        }
        const uint4* g2 = (const uint4*)b2;
        for (int r = tid; r < 192; r += 128) cpa16(base + S_B2 + r * 16, g2 + r);
        const uint4* gb = (const uint4*)(basis2 + (size_t)blk * 1024);
        for (int r = tid; r < 256; r += 128) cpa16(base + S_BAS + r * 16, gb + r);
        CP_COMMIT();
    }

    // ---- A fragments: direct coalesced LDG (latency overlaps tmp compute below) ----
    uint32_t aw[2][2][4][4];   // [hl][mt][kt][r]
    {
        const uint4* gA = g_Af + (size_t)(blk * 4 + wid) * 512;
#pragma unroll
        for (int hl = 0; hl < 2; hl++)
#pragma unroll
            for (int mt = 0; mt < 2; mt++)
#pragma unroll
                for (int kt = 0; kt < 4; kt++) {
                    uint4 v = __ldg(&gA[(size_t)((hl * 2 + mt) * 4 + kt) * 32 + lane]);
                    aw[hl][mt][kt][0] = v.x; aw[hl][mt][kt][1] = v.y;
                    aw[hl][mt][kt][2] = v.z; aw[hl][mt][kt][3] = v.w;
                }
    }

    // ---- fused tmp: tmp[e, m*2+l] = sum_d f[src,m,d]*basis1[e,d,l] ----
    {
        int e = blk * 128 + tid;
        int src = __ldg(&nbr[e]);
        const float4* fp = (const float4*)(f + (size_t)src * 32);
        float fr[8][4];
#pragma unroll
        for (int m = 0; m < 8; m++) {
            float4 v = __ldg(&fp[m]);
            fr[m][0] = v.x; fr[m][1] = v.y; fr[m][2] = v.z; fr[m][3] = v.w;
        }
        float4 b0 = __ldg((const float4*)(basis1 + (size_t)e * 8));
        float4 b1v = __ldg((const float4*)(basis1 + (size_t)e * 8 + 4));
        float bd[4][2] = {{b0.x, b0.y}, {b0.z, b0.w}, {b1v.x, b1v.y}, {b1v.z, b1v.w}};
        float* dst = (float*)(sm + S_TMP);
#pragma unroll
        for (int m = 0; m < 8; m++)
#pragma unroll
            for (int l = 0; l < 2; l++) {
                float a = fr[m][0] * bd[0][l];
                a = fmaf(fr[m][1], bd[1][l], a);
                a = fmaf(fr[m][2], bd[2][l], a);
                a = fmaf(fr[m][3], bd[3][l], a);
                dst[(m * 2 + l) * 128 + tid] = a;
            }
    }
    __syncthreads();           // tmp visible

    // ---- chunk-invariant tmp values: tr[rid][s], i = (s>>1)*8 + 2q + (s&1) ----
    float tr[4][4];
    {
        const float* sTMPf = (const float*)(sm + S_TMP);
#pragma unroll
        for (int rid = 0; rid < 4; rid++) {
            int row = wid * 32 + (lane >> 2) + rid * 8;
#pragma unroll
            for (int s = 0; s < 4; s++) {
                int i = (s >> 1) * 8 + 2 * q + (s & 1);
                tr[rid][s] = sTMPf[i * 128 + row];
            }
        }
    }

    float acc[2][8][4];
#pragma unroll
    for (int mt = 0; mt < 2; mt++)
#pragma unroll
        for (int nt = 0; nt < 8; nt++)
#pragma unroll
            for (int x = 0; x < 4; x++) acc[mt][nt][x] = 0.0f;

    for (int pr = 0; pr < 6; pr++) {
        CP_WAIT(0);
        __syncthreads();   // B pair pr visible; all warps done with pair pr-1; tr reads done (pr=0)

        if (pr < 5) {      // prefetch pair pr+1 into buf (pr+1)&1 (freed by the sync above)
            uint32_t dst = base + S_B + (uint32_t)((pr + 1) & 1) * 32768u;
            const uint4* bh = (const uint4*)g_Bfhi;
            const uint4* bl = (const uint4*)g_Bflo;
#pragma unroll
            for (int sc2 = 0; sc2 < 2; sc2++) {
                size_t ch = (size_t)((pr + 1) * 2 + sc2) * 512;
                for (int r = tid; r < 512; r += 128)
                    cpa16(dst + sc2 * 16384u + r * 16, bh + ch + r);
                for (int r = tid; r < 512; r += 128)
                    cpa16(dst + sc2 * 16384u + 8192u + r * 16, bl + ch + r);
            }
            CP_COMMIT();
        }

#pragma unroll
        for (int sc = 0; sc < 2; sc++) {
            int c = pr * 2 + sc;
            const unsigned char* bbuf = sm + S_B + (uint32_t)(pr & 1) * 32768u + (uint32_t)sc * 16384u;
#pragma unroll
            for (int kt = 0; kt < 4; kt++) {
#pragma unroll
                for (int nt = 0; nt < 8; nt++) {
                    uint32_t boff = (uint32_t)(((kt * 8 + nt) * 32 + lane) * 8);
                    uint2 bh = *(const uint2*)(bbuf + boff);
                    uint2 bl = *(const uint2*)(bbuf + 8192u + boff);
#pragma unroll
                    for (int mt = 0; mt < 2; mt++) {
                        mma16816(acc[mt][nt], aw[0][mt][kt], (const uint32_t*)&bh);
                        mma16816(acc[mt][nt], aw[0][mt][kt], (const uint32_t*)&bl);
                        mma16816(acc[mt][nt], aw[1][mt][kt], (const uint32_t*)&bh);
                    }
                }
            }

            // ---- fragment-direct epilogue ----
            float p[4][4];
#pragma unroll
            for (int rid = 0; rid < 4; rid++)
#pragma unroll
                for (int o = 0; o < 4; o++) p[rid][o] = 0.0f;
#pragma unroll
            for (int mt = 0; mt < 2; mt++)
#pragma unroll
                for (int nt = 0; nt < 8; nt++) {
                    int o = nt >> 1, s0 = (nt & 1) * 2;
                    float2 bb = *(const float2*)&sB2f[c * 64 + nt * 8 + q * 2];
#pragma unroll
                    for (int h = 0; h < 2; h++) {
                        int rid = mt * 2 + h;
                        p[rid][o] = fmaf(acc[mt][nt][h * 2] + bb.x, tr[rid][s0],
                                   fmaf(acc[mt][nt][h * 2 + 1] + bb.y, tr[rid][s0 + 1], p[rid][o]));
                        acc[mt][nt][h * 2] = 0.0f;
                        acc[mt][nt][h * 2 + 1] = 0.0f;
                    }
                }
#pragma unroll
            for (int rid = 0; rid < 4; rid++)
#pragma unroll
                for (int o = 0; o < 4; o++) {
                    p[rid][o] += __shfl_xor_sync(0xffffffffu, p[rid][o], 1);
                    p[rid][o] += __shfl_xor_sync(0xffffffffu, p[rid][o], 2);
                }

            if (c < 4 || c >= 8) {
                if (q == 0) {
                    int psm0 = (c < 4) ? (c * 2) : ((c - 8) * 2 + 8);
#pragma unroll
                    for (int rid = 0; rid < 4; rid++) {
                        int el = wid * 32 + (lane >> 2) + rid * 8;
                        float4 p0 = *(const float4*)(sm + S_BAS + el * 32);
                        float4 p1 = *(const float4*)(sm + S_BAS + el * 32 + 16);
#pragma unroll
                        for (int pl = 0; pl < 2; pl++) {
                            float a0 = p[rid][pl * 2], a1 = p[rid][pl * 2 + 1];
                            float4 o4;
                            o4.x = fmaf(a0, p0.x, a1 * p1.x);
                            o4.y = fmaf(a0, p0.y, a1 * p1.y);
                            o4.z = fmaf(a0, p0.z, a1 * p1.z);
                            o4.w = fmaf(a0, p0.w, a1 * p1.w);
                            *(float4*)(sm + S_KQV + (size_t)(psm0 + pl) * 2048 + el * 16) = o4;
                        }
                    }
                }
            } else {
                int qp0 = (c - 4) * 2;
                float4 an[2][2];
#pragma unroll
                for (int pl = 0; pl < 2; pl++)
#pragma unroll
                    for (int nn = 0; nn < 2; nn++) an[pl][nn] = make_float4(0.f, 0.f, 0.f, 0.f);
#pragma unroll
                for (int rid = 0; rid < 4; rid++) {
                    int el = wid * 32 + (lane >> 2) + rid * 8;
                    float4 p0 = *(const float4*)(sm + S_BAS + el * 32);
                    float4 p1 = *(const float4*)(sm + S_BAS + el * 32 + 16);
                    int nn = rid >> 1;
#pragma unroll
                    for (int pl = 0; pl < 2; pl++) {
                        float a0 = p[rid][pl * 2], a1 = p[rid][pl * 2 + 1];
                        an[pl][nn].x = fmaf(a0, p0.x, fmaf(a1, p1.x, an[pl][nn].x));
                        an[pl][nn].y = fmaf(a0, p0.y, fmaf(a1, p1.y, an[pl][nn].y));
                        an[pl][nn].z = fmaf(a0, p0.z, fmaf(a1, p1.z, an[pl][nn].z));
                        an[pl][nn].w = fmaf(a0, p0.w, fmaf(a1, p1.w, an[pl][nn].w));
                    }
                }
#pragma unroll
                for (int pl = 0; pl < 2; pl++)
#pragma unroll
                    for (int nn = 0; nn < 2; nn++) {
#pragma unroll
                        for (int d = 4; d <= 16; d <<= 1) {
                            an[pl][nn].x += __shfl_xor_sync(0xffffffffu, an[pl][nn].x, d);
                            an[pl][nn].y += __shfl_xor_sync(0xffffffffu, an[pl][nn].y, d);
                            an[pl][nn].z += __shfl_xor_sync(0xffffffffu, an[pl][nn].z, d);
                            an[pl][nn].w += __shfl_xor_sync(0xffffffffu, an[pl][nn].w, d);
                        }
                    }
                if (lane == 0) {
#pragma unroll
                    for (int pl = 0; pl < 2; pl++)
#pragma unroll
                        for (int nn = 0; nn < 2; nn++)
                            *(float4*)(sm + S_QN + (size_t)((wid * 2 + nn) * 8 + qp0 + pl) * 16)
                                = an[pl][nn];
                }
            }
        }
    }

    // ---- in-CTA attention: 8 nodes, 16 lanes per node (register-light 2-pass) ----
    __syncthreads();
    {
        int k16 = lane & 15, nh = lane >> 4;
        int nl = wid * 2 + nh;
        int n = blk * 8 + nl;
        int el = nl * 16 + k16;
        float s[4] = {0.f, 0.f, 0.f, 0.f};
#pragma unroll
        for (int pp = 0; pp < 8; pp++) {
            float4 kv = *(const float4*)(sm + S_KQV + (size_t)pp * 2048 + el * 16);
            float4 qv = *(const float4*)(sm + S_QN + (size_t)(nl * 8 + pp) * 16);
            s[pp >> 1] = fmaf(kv.x, qv.x, fmaf(kv.y, qv.y,
                         fmaf(kv.z, qv.z, fmaf(kv.w, qv.w, s[pp >> 1]))));
        }
        const float scale = 0.35355339059327373f * 0.0625f;  // 8^-0.5 * 1/16 (q mean)
#pragma unroll
        for (int h = 0; h < 4; h++) {
            s[h] *= scale;
            float m = s[h];
#pragma unroll
            for (int d = 1; d < 16; d <<= 1)
                m = fmaxf(m, __shfl_xor_sync(0xffffffffu, m, d));
            float w = __expf(s[h] - m);
            float z = w;
#pragma unroll
            for (int d = 1; d < 16; d <<= 1)
                z += __shfl_xor_sync(0xffffffffu, z, d);
            s[h] = w / z;
        }
#pragma unroll
        for (int pp = 0; pp < 8; pp++) {
            float4 vv = *(const float4*)(sm + S_KQV + (size_t)(8 + pp) * 2048 + el * 16);
            float w = s[pp >> 1];
            float4 o4 = make_float4(w * vv.x, w * vv.y, w * vv.z, w * vv.w);
#pragma unroll
            for (int d = 1; d < 16; d <<= 1) {
                o4.x += __shfl_xor_sync(0xffffffffu, o4.x, d);
                o4.y += __shfl_xor_sync(0xffffffffu, o4.y, d);
                o4.z += __shfl_xor_sync(0xffffffffu, o4.z, d);
                o4.w += __shfl_xor_sync(0xffffffffu, o4.w, d);
            }
            if (k16 == 0)
                *(float4*)(out + (size_t)n * 32 + pp * 4) = o4;
        }
    }
}

extern "C" void kernel_launch(void* const* d_in, const int* in_sizes, int n_in,
                              void* d_out, int out_size) {
    const float* basis1 = (const float*)d_in[0];
    const float* basis2 = (const float*)d_in[1];
    const float* ef     = (const float*)d_in[2];
    const float* f      = (const float*)d_in[3];
    const float* W1     = (const float*)d_in[4];
    const float* b1     = (const float*)d_in[5];
    const float* W2     = (const float*)d_in[6];
    const float* b2     = (const float*)d_in[7];
    const int*   nbr    = (const int*)d_in[8];
    float* out = (float*)d_out;

    cudaFuncSetAttribute(k_main, cudaFuncAttributeMaxDynamicSharedMemorySize, SMEM_SZ);

    k_mlp1<<<EN / 32, 128>>>(ef, W1, b1, W2);
    k_main<<<EN / 128, 128, SMEM_SZ>>>(b2, basis2, basis1, f, nbr, out);
}

// round 8
// speedup vs baseline: 3.8203x; 1.2443x over previous
#include <cuda_runtime.h>
#include <cuda_bf16.h>
#include <cstdint>

#define EN 160000      // edges = N*K
#define NN 10000       // nodes

// ---------------- static device scratch -----------------------------------------------------
__device__ __align__(16) uint2 g_Bfhi[12 * 1024];   // W2 hi, m16n8k16 B-frag [chunk][kt][nt][lane]
__device__ __align__(16) uint2 g_Bflo[12 * 1024];   // W2 lo
__device__ __align__(16) uint2 g_W1fhi[512];        // W1 hi, B-frag [kt(2)][nt(8)][lane]
__device__ __align__(16) uint2 g_W1flo[512];        // W1 lo

// ---------------- helpers --------------------------------------------------------------------
__device__ __forceinline__ uint32_t smem_u32(const void* p) {
    uint32_t a;
    asm("{ .reg .u64 t; cvta.to.shared.u64 t, %1; cvt.u32.u64 %0, t; }" : "=r"(a) : "l"(p));
    return a;
}
__device__ __forceinline__ void mma16816(float* c, const uint32_t* a, const uint32_t* b) {
    asm volatile("mma.sync.aligned.m16n8k16.row.col.f32.bf16.bf16.f32 "
        "{%0,%1,%2,%3}, {%4,%5,%6,%7}, {%8,%9}, {%0,%1,%2,%3};"
        : "+f"(c[0]), "+f"(c[1]), "+f"(c[2]), "+f"(c[3])
        : "r"(a[0]), "r"(a[1]), "r"(a[2]), "r"(a[3]), "r"(b[0]), "r"(b[1]));
}
__device__ __forceinline__ void cpa16(uint32_t dst, const void* src) {
    asm volatile("cp.async.cg.shared.global [%0], [%1], 16;" :: "r"(dst), "l"(src));
}
#define CP_COMMIT() asm volatile("cp.async.commit_group;" ::: "memory")
#define CP_WAIT(n)  asm volatile("cp.async.wait_group %0;" :: "n"(n) : "memory")

__device__ __forceinline__ void split2(float a, float b, uint32_t& h, uint32_t& l) {
    __nv_bfloat16 ah = __float2bfloat16(a), bh = __float2bfloat16(b);
    __nv_bfloat16 al = __float2bfloat16(a - __bfloat162float(ah));
    __nv_bfloat16 bl = __float2bfloat16(b - __bfloat162float(bh));
    h = (uint32_t)__bfloat16_as_ushort(ah) | ((uint32_t)__bfloat16_as_ushort(bh) << 16);
    l = (uint32_t)__bfloat16_as_ushort(al) | ((uint32_t)__bfloat16_as_ushort(bl) << 16);
}

// ---------------- Kernel P: pack W2 (12 blocks) and W1 (block 12) into B-frag layout ---------
__global__ void k_prep(const float* __restrict__ W2, const float* __restrict__ W1) {
    int bid = blockIdx.x, tid = threadIdx.x;
    if (bid < 12) {
        int c = bid;
        for (int idx = tid; idx < 1024; idx += 128) {
            int kt = idx >> 8, nt = (idx >> 5) & 7, l = idx & 31;
            int row = c * 64 + nt * 8 + (l >> 2);
            int j0 = kt * 16 + (l & 3) * 2;
            const float* wr = W2 + (size_t)row * 64;
            uint32_t h0, l0, h1, l1;
            split2(__ldg(&wr[j0]),     __ldg(&wr[j0 + 1]), h0, l0);
            split2(__ldg(&wr[j0 + 8]), __ldg(&wr[j0 + 9]), h1, l1);
            g_Bfhi[c * 1024 + idx] = make_uint2(h0, h1);
            g_Bflo[c * 1024 + idx] = make_uint2(l0, l1);
        }
    } else {
        for (int idx = tid; idx < 512; idx += 128) {
            int kt = idx >> 8, nt = (idx >> 5) & 7, l = idx & 31;
            int j = nt * 8 + (l >> 2);          // N dim = hidden j (64)
            int c0 = kt * 16 + (l & 3) * 2;     // K dim = edge-feat c (32)
            const float* wr = W1 + (size_t)j * 32;
            uint32_t h0, l0, h1, l1;
            split2(__ldg(&wr[c0]),     __ldg(&wr[c0 + 1]), h0, l0);
            split2(__ldg(&wr[c0 + 8]), __ldg(&wr[c0 + 9]), h1, l1);
            g_W1fhi[idx] = make_uint2(h0, h1);
            g_W1flo[idx] = make_uint2(l0, l1);
        }
    }
}

// ---------------- Kernel A: MLP(HMMA) + GEMM(HMMA) + tmp + epilogue + in-CTA attention -------
// CTA = 128 edges = 8 nodes. h computed on tensor cores; C frags transform in-register into
// the main GEMM's A frags. Chunk-pair B pipeline, 6 syncs.
#define S_KQV  0u              // 16 planes x 128 x 16B = 32768 (tmp 8K aliases planes 0-3)
#define S_TMP  0u
#define S_QN   32768u          // 1024
#define S_B    33792u          // 2 pair-bufs x 32768; within pair: sc*16384, hi +0, lo +8192
#define S_EF   33792u          // prologue scratch (aliases S_B): ef 128 x 36f = 18432
#define S_W1F  52224u          // W1 frags: hi 4096 + lo 4096
#define S_B1   60416u          // b1: 256
#define S_B2   99328u          // 3072
#define S_BAS  102400u         // 4096
#define SMEM_SZ (106496u + 1024u)

__global__ void __launch_bounds__(128, 2) k_main(const float* __restrict__ b2,
                                                 const float* __restrict__ basis2,
                                                 const float* __restrict__ basis1,
                                                 const float* __restrict__ f,
                                                 const int* __restrict__ nbr,
                                                 const float* __restrict__ ef,
                                                 const float* __restrict__ b1,
                                                 float* __restrict__ out) {
    extern __shared__ unsigned char smraw[];
    uint32_t base = (smem_u32(smraw) + 1023u) & ~1023u;
    unsigned char* sm = smraw + (base - smem_u32(smraw));
    const float* sB2f = (const float*)(sm + S_B2);
    int tid = threadIdx.x, blk = blockIdx.x;
    int wid = tid >> 5, lane = tid & 31;
    int q = lane & 3;

    // ---- G0: ef tile + W1 frags + b1 + b2 + basis2 ----
    {
        for (int r = tid; r < 1024; r += 128) {
            int row = r >> 3, seg = r & 7;
            cpa16(base + S_EF + (uint32_t)row * 144u + (uint32_t)seg * 16u,
                  ef + ((size_t)(blk * 128 + row)) * 32 + seg * 4);
        }
        const uint4* wh = (const uint4*)g_W1fhi;
        const uint4* wl = (const uint4*)g_W1flo;
        for (int r = tid; r < 256; r += 128) cpa16(base + S_W1F + r * 16, wh + r);
        for (int r = tid; r < 256; r += 128) cpa16(base + S_W1F + 4096u + r * 16, wl + r);
        const uint4* g1 = (const uint4*)b1;
        for (int r = tid; r < 16; r += 128) cpa16(base + S_B1 + r * 16, g1 + r);
        const uint4* g2 = (const uint4*)b2;
        for (int r = tid; r < 192; r += 128) cpa16(base + S_B2 + r * 16, g2 + r);
        const uint4* gb = (const uint4*)(basis2 + (size_t)blk * 1024);
        for (int r = tid; r < 256; r += 128) cpa16(base + S_BAS + r * 16, gb + r);
        CP_COMMIT();
    }
    CP_WAIT(0);
    __syncthreads();

    // ---- MLP on tensor cores: h = relu(ef @ W1^T + b1), C frags -> A frags in-register ----
    uint32_t awh[2][4][4], awl[2][4][4];   // main-GEMM A frags [mt][kt][r]
    {
        // ef A-frags (K=32: kt 0..1), split bf16
        uint32_t efh[2][2][4], efl[2][2][4];
        const float* sEF = (const float*)(sm + S_EF);
#pragma unroll
        for (int mt = 0; mt < 2; mt++)
#pragma unroll
            for (int kt = 0; kt < 2; kt++) {
                int r0 = wid * 32 + mt * 16 + (lane >> 2);
                int c0 = kt * 16 + 2 * q;
                float2 v0 = *(const float2*)&sEF[r0 * 36 + c0];
                float2 v1 = *(const float2*)&sEF[(r0 + 8) * 36 + c0];
                float2 v2 = *(const float2*)&sEF[r0 * 36 + c0 + 8];
                float2 v3 = *(const float2*)&sEF[(r0 + 8) * 36 + c0 + 8];
                split2(v0.x, v0.y, efh[mt][kt][0], efl[mt][kt][0]);
                split2(v1.x, v1.y, efh[mt][kt][1], efl[mt][kt][1]);
                split2(v2.x, v2.y, efh[mt][kt][2], efl[mt][kt][2]);
                split2(v3.x, v3.y, efh[mt][kt][3], efl[mt][kt][3]);
            }
        float hc[2][8][4];
#pragma unroll
        for (int mt = 0; mt < 2; mt++)
#pragma unroll
            for (int nt = 0; nt < 8; nt++)
#pragma unroll
                for (int x = 0; x < 4; x++) hc[mt][nt][x] = 0.0f;
#pragma unroll
        for (int kt = 0; kt < 2; kt++)
#pragma unroll
            for (int ps = 0; ps < 3; ps++) {
                uint32_t off = (ps == 1) ? 4096u : 0u;
#pragma unroll
                for (int nt = 0; nt < 8; nt++) {
                    uint2 w = *(const uint2*)(sm + S_W1F + off + (uint32_t)(((kt * 8 + nt) * 32 + lane) * 8));
#pragma unroll
                    for (int mt = 0; mt < 2; mt++)
                        mma16816(hc[mt][nt], (ps == 2) ? efl[mt][kt] : efh[mt][kt],
                                 (const uint32_t*)&w);
                }
            }
        // + b1, relu, split-pack into A frags
        const float* sb1 = (const float*)(sm + S_B1);
#pragma unroll
        for (int nt = 0; nt < 8; nt++) {
            float ba = sb1[nt * 8 + 2 * q], bb = sb1[nt * 8 + 2 * q + 1];
            int kt = nt >> 1, rg = (nt & 1) * 2;
#pragma unroll
            for (int mt = 0; mt < 2; mt++) {
                float x0 = fmaxf(hc[mt][nt][0] + ba, 0.f);
                float x1 = fmaxf(hc[mt][nt][1] + bb, 0.f);
                float x2 = fmaxf(hc[mt][nt][2] + ba, 0.f);
                float x3 = fmaxf(hc[mt][nt][3] + bb, 0.f);
                split2(x0, x1, awh[mt][kt][rg],     awl[mt][kt][rg]);
                split2(x2, x3, awh[mt][kt][rg + 1], awl[mt][kt][rg + 1]);
            }
        }
    }
    __syncthreads();           // ef/W1F scratch free -> B buffers may be written

    // ---- B pair0 cp.async (overlaps tmp compute) ----
    {
        const uint4* bh = (const uint4*)g_Bfhi;
        const uint4* bl = (const uint4*)g_Bflo;
#pragma unroll
        for (int sc = 0; sc < 2; sc++) {
            for (int r = tid; r < 512; r += 128)
                cpa16(base + S_B + sc * 16384u + r * 16, bh + (size_t)sc * 512 + r);
            for (int r = tid; r < 512; r += 128)
                cpa16(base + S_B + sc * 16384u + 8192u + r * 16, bl + (size_t)sc * 512 + r);
        }
        CP_COMMIT();
    }

    // ---- tmp: tmp[e, m*2+l] = sum_d f[src,m,d]*basis1[e,d,l] ----
    {
        int e = blk * 128 + tid;
        int src = __ldg(&nbr[e]);
        const float4* fp = (const float4*)(f + (size_t)src * 32);
        float fr[8][4];
#pragma unroll
        for (int m = 0; m < 8; m++) {
            float4 v = __ldg(&fp[m]);
            fr[m][0] = v.x; fr[m][1] = v.y; fr[m][2] = v.z; fr[m][3] = v.w;
        }
        float4 b0 = __ldg((const float4*)(basis1 + (size_t)e * 8));
        float4 b1v = __ldg((const float4*)(basis1 + (size_t)e * 8 + 4));
        float bd[4][2] = {{b0.x, b0.y}, {b0.z, b0.w}, {b1v.x, b1v.y}, {b1v.z, b1v.w}};
        float* dst = (float*)(sm + S_TMP);
#pragma unroll
        for (int m = 0; m < 8; m++)
#pragma unroll
            for (int l = 0; l < 2; l++) {
                float a = fr[m][0] * bd[0][l];
                a = fmaf(fr[m][1], bd[1][l], a);
                a = fmaf(fr[m][2], bd[2][l], a);
                a = fmaf(fr[m][3], bd[3][l], a);
                dst[(m * 2 + l) * 128 + tid] = a;
            }
    }
    __syncthreads();           // tmp visible

    float tr[4][4];
    {
        const float* sTMPf = (const float*)(sm + S_TMP);
#pragma unroll
        for (int rid = 0; rid < 4; rid++) {
            int row = wid * 32 + (lane >> 2) + rid * 8;
#pragma unroll
            for (int s = 0; s < 4; s++) {
                int i = (s >> 1) * 8 + 2 * q + (s & 1);
                tr[rid][s] = sTMPf[i * 128 + row];
            }
        }
    }

    float acc[2][8][4];
#pragma unroll
    for (int mt = 0; mt < 2; mt++)
#pragma unroll
        for (int nt = 0; nt < 8; nt++)
#pragma unroll
            for (int x = 0; x < 4; x++) acc[mt][nt][x] = 0.0f;

    for (int pr = 0; pr < 6; pr++) {
        CP_WAIT(0);
        __syncthreads();   // B pair pr visible; all warps done with pair pr-1; tr reads done

        if (pr < 5) {      // prefetch pair pr+1 into buf (pr+1)&1
            uint32_t dst = base + S_B + (uint32_t)((pr + 1) & 1) * 32768u;
            const uint4* bh = (const uint4*)g_Bfhi;
            const uint4* bl = (const uint4*)g_Bflo;
#pragma unroll
            for (int sc2 = 0; sc2 < 2; sc2++) {
                size_t ch = (size_t)((pr + 1) * 2 + sc2) * 512;
                for (int r = tid; r < 512; r += 128)
                    cpa16(dst + sc2 * 16384u + r * 16, bh + ch + r);
                for (int r = tid; r < 512; r += 128)
                    cpa16(dst + sc2 * 16384u + 8192u + r * 16, bl + ch + r);
            }
            CP_COMMIT();
        }

#pragma unroll
        for (int sc = 0; sc < 2; sc++) {
            int c = pr * 2 + sc;
            const unsigned char* bbuf = sm + S_B + (uint32_t)(pr & 1) * 32768u + (uint32_t)sc * 16384u;
            // pass-major: per-acc HMMA chains at distance 16 (ILP)
#pragma unroll
            for (int kt = 0; kt < 4; kt++)
#pragma unroll
                for (int ps = 0; ps < 3; ps++) {
                    uint32_t off = (ps == 1) ? 8192u : 0u;
#pragma unroll
                    for (int nt = 0; nt < 8; nt++) {
                        uint2 b = *(const uint2*)(bbuf + off + (uint32_t)(((kt * 8 + nt) * 32 + lane) * 8));
#pragma unroll
                        for (int mt = 0; mt < 2; mt++)
                            mma16816(acc[mt][nt], (ps == 2) ? awl[mt][kt] : awh[mt][kt],
                                     (const uint32_t*)&b);
                    }
                }

            // ---- fragment-direct epilogue ----
            float p[4][4];
#pragma unroll
            for (int rid = 0; rid < 4; rid++)
#pragma unroll
                for (int o = 0; o < 4; o++) p[rid][o] = 0.0f;
#pragma unroll
            for (int mt = 0; mt < 2; mt++)
#pragma unroll
                for (int nt = 0; nt < 8; nt++) {
                    int o = nt >> 1, s0 = (nt & 1) * 2;
                    float2 bb = *(const float2*)&sB2f[c * 64 + nt * 8 + q * 2];
#pragma unroll
                    for (int h = 0; h < 2; h++) {
                        int rid = mt * 2 + h;
                        p[rid][o] = fmaf(acc[mt][nt][h * 2] + bb.x, tr[rid][s0],
                                   fmaf(acc[mt][nt][h * 2 + 1] + bb.y, tr[rid][s0 + 1], p[rid][o]));
                        acc[mt][nt][h * 2] = 0.0f;
                        acc[mt][nt][h * 2 + 1] = 0.0f;
                    }
                }
#pragma unroll
            for (int rid = 0; rid < 4; rid++)
#pragma unroll
                for (int o = 0; o < 4; o++) {
                    p[rid][o] += __shfl_xor_sync(0xffffffffu, p[rid][o], 1);
                    p[rid][o] += __shfl_xor_sync(0xffffffffu, p[rid][o], 2);
                }

            if (c < 4 || c >= 8) {
                if (q == 0) {
                    int psm0 = (c < 4) ? (c * 2) : ((c - 8) * 2 + 8);
#pragma unroll
                    for (int rid = 0; rid < 4; rid++) {
                        int el = wid * 32 + (lane >> 2) + rid * 8;
                        float4 p0 = *(const float4*)(sm + S_BAS + el * 32);
                        float4 p1 = *(const float4*)(sm + S_BAS + el * 32 + 16);
#pragma unroll
                        for (int pl = 0; pl < 2; pl++) {
                            float a0 = p[rid][pl * 2], a1 = p[rid][pl * 2 + 1];
                            float4 o4;
                            o4.x = fmaf(a0, p0.x, a1 * p1.x);
                            o4.y = fmaf(a0, p0.y, a1 * p1.y);
                            o4.z = fmaf(a0, p0.z, a1 * p1.z);
                            o4.w = fmaf(a0, p0.w, a1 * p1.w);
                            *(float4*)(sm + S_KQV + (size_t)(psm0 + pl) * 2048 + el * 16) = o4;
                        }
                    }
                }
            } else {
                int qp0 = (c - 4) * 2;
                float4 an[2][2];
#pragma unroll
                for (int pl = 0; pl < 2; pl++)
#pragma unroll
                    for (int nn = 0; nn < 2; nn++) an[pl][nn] = make_float4(0.f, 0.f, 0.f, 0.f);
#pragma unroll
                for (int rid = 0; rid < 4; rid++) {
                    int el = wid * 32 + (lane >> 2) + rid * 8;
                    float4 p0 = *(const float4*)(sm + S_BAS + el * 32);
                    float4 p1 = *(const float4*)(sm + S_BAS + el * 32 + 16);
                    int nn = rid >> 1;
#pragma unroll
                    for (int pl = 0; pl < 2; pl++) {
                        float a0 = p[rid][pl * 2], a1 = p[rid][pl * 2 + 1];
                        an[pl][nn].x = fmaf(a0, p0.x, fmaf(a1, p1.x, an[pl][nn].x));
                        an[pl][nn].y = fmaf(a0, p0.y, fmaf(a1, p1.y, an[pl][nn].y));
                        an[pl][nn].z = fmaf(a0, p0.z, fmaf(a1, p1.z, an[pl][nn].z));
                        an[pl][nn].w = fmaf(a0, p0.w, fmaf(a1, p1.w, an[pl][nn].w));
                    }
                }
#pragma unroll
                for (int pl = 0; pl < 2; pl++)
#pragma unroll
                    for (int nn = 0; nn < 2; nn++) {
#pragma unroll
                        for (int d = 4; d <= 16; d <<= 1) {
                            an[pl][nn].x += __shfl_xor_sync(0xffffffffu, an[pl][nn].x, d);
                            an[pl][nn].y += __shfl_xor_sync(0xffffffffu, an[pl][nn].y, d);
                            an[pl][nn].z += __shfl_xor_sync(0xffffffffu, an[pl][nn].z, d);
                            an[pl][nn].w += __shfl_xor_sync(0xffffffffu, an[pl][nn].w, d);
                        }
                    }
                if (lane == 0) {
#pragma unroll
                    for (int pl = 0; pl < 2; pl++)
#pragma unroll
                        for (int nn = 0; nn < 2; nn++)
                            *(float4*)(sm + S_QN + (size_t)((wid * 2 + nn) * 8 + qp0 + pl) * 16)
                                = an[pl][nn];
                }
            }
        }
    }

    // ---- in-CTA attention: 8 nodes, 16 lanes per node ----
    __syncthreads();
    {
        int k16 = lane & 15, nh = lane >> 4;
        int nl = wid * 2 + nh;
        int n = blk * 8 + nl;
        int el = nl * 16 + k16;
        float s[4] = {0.f, 0.f, 0.f, 0.f};
#pragma unroll
        for (int pp = 0; pp < 8; pp++) {
            float4 kv = *(const float4*)(sm + S_KQV + (size_t)pp * 2048 + el * 16);
            float4 qv = *(const float4*)(sm + S_QN + (size_t)(nl * 8 + pp) * 16);
            s[pp >> 1] = fmaf(kv.x, qv.x, fmaf(kv.y, qv.y,
                         fmaf(kv.z, qv.z, fmaf(kv.w, qv.w, s[pp >> 1]))));
        }
        const float scale = 0.35355339059327373f * 0.0625f;  // 8^-0.5 * 1/16 (q mean)
#pragma unroll
        for (int h = 0; h < 4; h++) {
            s[h] *= scale;
            float m = s[h];
#pragma unroll
            for (int d = 1; d < 16; d <<= 1)
                m = fmaxf(m, __shfl_xor_sync(0xffffffffu, m, d));
            float w = __expf(s[h] - m);
            float z = w;
#pragma unroll
            for (int d = 1; d < 16; d <<= 1)
                z += __shfl_xor_sync(0xffffffffu, z, d);
            s[h] = w / z;
        }
#pragma unroll
        for (int pp = 0; pp < 8; pp++) {
            float4 vv = *(const float4*)(sm + S_KQV + (size_t)(8 + pp) * 2048 + el * 16);
            float w = s[pp >> 1];
            float4 o4 = make_float4(w * vv.x, w * vv.y, w * vv.z, w * vv.w);
#pragma unroll
            for (int d = 1; d < 16; d <<= 1) {
                o4.x += __shfl_xor_sync(0xffffffffu, o4.x, d);
                o4.y += __shfl_xor_sync(0xffffffffu, o4.y, d);
                o4.z += __shfl_xor_sync(0xffffffffu, o4.z, d);
                o4.w += __shfl_xor_sync(0xffffffffu, o4.w, d);
            }
            if (k16 == 0)
                *(float4*)(out + (size_t)n * 32 + pp * 4) = o4;
        }
    }
}

extern "C" void kernel_launch(void* const* d_in, const int* in_sizes, int n_in,
                              void* d_out, int out_size) {
    const float* basis1 = (const float*)d_in[0];
    const float* basis2 = (const float*)d_in[1];
    const float* ef     = (const float*)d_in[2];
    const float* f      = (const float*)d_in[3];
    const float* W1     = (const float*)d_in[4];
    const float* b1     = (const float*)d_in[5];
    const float* W2     = (const float*)d_in[6];
    const float* b2     = (const float*)d_in[7];
    const int*   nbr    = (const int*)d_in[8];
    float* out = (float*)d_out;

    cudaFuncSetAttribute(k_main, cudaFuncAttributeMaxDynamicSharedMemorySize, SMEM_SZ);

    k_prep<<<13, 128>>>(W2, W1);
    k_main<<<EN / 128, 128, SMEM_SZ>>>(b2, basis2, basis1, f, nbr, ef, b1, out);
}

// round 9
// speedup vs baseline: 4.2654x; 1.1165x over previous
#include <cuda_runtime.h>
#include <cuda_bf16.h>
#include <cstdint>

#define EN 160000      // edges = N*K
#define NN 10000       // nodes

// ---------------- static device scratch -----------------------------------------------------
__device__ __align__(16) uint4 g_Bf[12 * 1024];   // W2 packed {hi0,hi1,lo0,lo1} [chunk][kt][nt][lane]
__device__ __align__(16) uint4 g_W1f[512];        // W1 packed [kt2(2)][nt(8)][lane]

// ---------------- helpers --------------------------------------------------------------------
__device__ __forceinline__ uint32_t smem_u32(const void* p) {
    uint32_t a;
    asm("{ .reg .u64 t; cvta.to.shared.u64 t, %1; cvt.u32.u64 %0, t; }" : "=r"(a) : "l"(p));
    return a;
}
__device__ __forceinline__ void mma16816(float* c, const uint32_t* a, const uint32_t* b) {
    asm volatile("mma.sync.aligned.m16n8k16.row.col.f32.bf16.bf16.f32 "
        "{%0,%1,%2,%3}, {%4,%5,%6,%7}, {%8,%9}, {%0,%1,%2,%3};"
        : "+f"(c[0]), "+f"(c[1]), "+f"(c[2]), "+f"(c[3])
        : "r"(a[0]), "r"(a[1]), "r"(a[2]), "r"(a[3]), "r"(b[0]), "r"(b[1]));
}
__device__ __forceinline__ void cpa16(uint32_t dst, const void* src) {
    asm volatile("cp.async.cg.shared.global [%0], [%1], 16;" :: "r"(dst), "l"(src));
}
#define CP_COMMIT() asm volatile("cp.async.commit_group;" ::: "memory")
#define CP_WAIT(n)  asm volatile("cp.async.wait_group %0;" :: "n"(n) : "memory")

__device__ __forceinline__ void split2(float a, float b, uint32_t& h, uint32_t& l) {
    __nv_bfloat16 ah = __float2bfloat16(a), bh = __float2bfloat16(b);
    __nv_bfloat16 al = __float2bfloat16(a - __bfloat162float(ah));
    __nv_bfloat16 bl = __float2bfloat16(b - __bfloat162float(bh));
    h = (uint32_t)__bfloat16_as_ushort(ah) | ((uint32_t)__bfloat16_as_ushort(bh) << 16);
    l = (uint32_t)__bfloat16_as_ushort(al) | ((uint32_t)__bfloat16_as_ushort(bl) << 16);
}

// ---------------- Kernel P: pack W2 (12 blocks) and W1 (block 12), hi/lo interleaved ---------
__global__ void k_prep(const float* __restrict__ W2, const float* __restrict__ W1) {
    int bid = blockIdx.x, tid = threadIdx.x;
    if (bid < 12) {
        int c = bid;
        for (int idx = tid; idx < 1024; idx += 128) {
            int kt = idx >> 8, nt = (idx >> 5) & 7, l = idx & 31;
            int row = c * 64 + nt * 8 + (l >> 2);
            int j0 = kt * 16 + (l & 3) * 2;
            const float* wr = W2 + (size_t)row * 64;
            uint4 v;
            split2(__ldg(&wr[j0]),     __ldg(&wr[j0 + 1]), v.x, v.z);
            split2(__ldg(&wr[j0 + 8]), __ldg(&wr[j0 + 9]), v.y, v.w);
            g_Bf[c * 1024 + idx] = v;
        }
    } else {
        for (int idx = tid; idx < 512; idx += 128) {
            int kt = idx >> 8, nt = (idx >> 5) & 7, l = idx & 31;
            int j = nt * 8 + (l >> 2);          // N dim = hidden j (64)
            int c0 = kt * 16 + (l & 3) * 2;     // K dim = edge-feat c (32)
            const float* wr = W1 + (size_t)j * 32;
            uint4 v;
            split2(__ldg(&wr[c0]),     __ldg(&wr[c0 + 1]), v.x, v.z);
            split2(__ldg(&wr[c0 + 8]), __ldg(&wr[c0 + 9]), v.y, v.w);
            g_W1f[idx] = v;
        }
    }
}

// ---------------- Kernel A: MLP(HMMA) + GEMM(HMMA) + tmp + epilogue + in-CTA attention -------
// CTA = 128 edges = 8 nodes; 3 CTAs/SM. nt split into halves: acc 32 regs, each half emits
// one complete output plane. Chunk-granular B double buffer (2x16KB), 12 waits/syncs.
#define S_KQV  0u              // 16 planes x 128 x 16B = 32768 (tmp 8K aliases planes 0-3)
#define S_TMP  0u
#define S_QN   32768u          // 1024
#define S_B    33792u          // 2 chunk-bufs x 16384 (packed hi/lo)   ..66560
#define S_EF   33792u          // prologue scratch (aliases S_B): 128 x 144B = 18432
#define S_W1F  52224u          // W1 frags packed: 8192  ..60416
#define S_B1   60416u          // b1: 256
#define S_B2   66560u          // 3072  ..69632
#define S_BAS  69632u          // 4096  ..73728
#define SMEM_SZ (73728u + 1024u)

__global__ void __launch_bounds__(128, 3) k_main(const float* __restrict__ b2,
                                                 const float* __restrict__ basis2,
                                                 const float* __restrict__ basis1,
                                                 const float* __restrict__ f,
                                                 const int* __restrict__ nbr,
                                                 const float* __restrict__ ef,
                                                 const float* __restrict__ b1,
                                                 float* __restrict__ out) {
    extern __shared__ unsigned char smraw[];
    uint32_t base = (smem_u32(smraw) + 1023u) & ~1023u;
    unsigned char* sm = smraw + (base - smem_u32(smraw));
    const float* sB2f = (const float*)(sm + S_B2);
    int tid = threadIdx.x, blk = blockIdx.x;
    int wid = tid >> 5, lane = tid & 31;
    int q = lane & 3;

    // ---- G_pre: ef tile + W1 frags + b1 + b2 + basis2 ----
    {
        for (int r = tid; r < 1024; r += 128) {
            int row = r >> 3, seg = r & 7;
            cpa16(base + S_EF + (uint32_t)row * 144u + (uint32_t)seg * 16u,
                  ef + ((size_t)(blk * 128 + row)) * 32 + seg * 4);
        }
        const uint4* wf = (const uint4*)g_W1f;
        for (int r = tid; r < 512; r += 128) cpa16(base + S_W1F + r * 16, wf + r);
        const uint4* g1 = (const uint4*)b1;
        for (int r = tid; r < 16; r += 128) cpa16(base + S_B1 + r * 16, g1 + r);
        const uint4* g2 = (const uint4*)b2;
        for (int r = tid; r < 192; r += 128) cpa16(base + S_B2 + r * 16, g2 + r);
        const uint4* gb = (const uint4*)(basis2 + (size_t)blk * 1024);
        for (int r = tid; r < 256; r += 128) cpa16(base + S_BAS + r * 16, gb + r);
        CP_COMMIT();
    }
    CP_WAIT(0);
    __syncthreads();

    // ---- MLP on tensor cores: h = relu(ef @ W1^T + b1) -> A frags in-register ----
    uint32_t awh[2][4][4], awl[2][4][4];   // main-GEMM A frags [mt][kt][r]
    {
        uint32_t efh[2][2][4], efl[2][2][4];
        const float* sEF = (const float*)(sm + S_EF);
#pragma unroll
        for (int mt = 0; mt < 2; mt++)
#pragma unroll
            for (int kt = 0; kt < 2; kt++) {
                int r0 = wid * 32 + mt * 16 + (lane >> 2);
                int c0 = kt * 16 + 2 * q;
                float2 v0 = *(const float2*)&sEF[r0 * 36 + c0];
                float2 v1 = *(const float2*)&sEF[(r0 + 8) * 36 + c0];
                float2 v2 = *(const float2*)&sEF[r0 * 36 + c0 + 8];
                float2 v3 = *(const float2*)&sEF[(r0 + 8) * 36 + c0 + 8];
                split2(v0.x, v0.y, efh[mt][kt][0], efl[mt][kt][0]);
                split2(v1.x, v1.y, efh[mt][kt][1], efl[mt][kt][1]);
                split2(v2.x, v2.y, efh[mt][kt][2], efl[mt][kt][2]);
                split2(v3.x, v3.y, efh[mt][kt][3], efl[mt][kt][3]);
            }
        const float* sb1 = (const float*)(sm + S_B1);
#pragma unroll
        for (int nth = 0; nth < 2; nth++) {
            float hc[2][4][4];
#pragma unroll
            for (int mt = 0; mt < 2; mt++)
#pragma unroll
                for (int n4 = 0; n4 < 4; n4++)
#pragma unroll
                    for (int x = 0; x < 4; x++) hc[mt][n4][x] = 0.0f;
#pragma unroll
            for (int kt2 = 0; kt2 < 2; kt2++) {
                uint4 w[4];
#pragma unroll
                for (int n4 = 0; n4 < 4; n4++)
                    w[n4] = *(const uint4*)(sm + S_W1F +
                        (uint32_t)(((kt2 * 8 + nth * 4 + n4) * 32 + lane) * 16));
#pragma unroll
                for (int ps = 0; ps < 3; ps++)
#pragma unroll
                    for (int n4 = 0; n4 < 4; n4++) {
                        const uint32_t* bp = (ps == 1) ? &w[n4].z : &w[n4].x;
#pragma unroll
                        for (int mt = 0; mt < 2; mt++)
                            mma16816(hc[mt][n4], (ps == 2) ? efl[mt][kt2] : efh[mt][kt2], bp);
                    }
            }
#pragma unroll
            for (int n4 = 0; n4 < 4; n4++) {
                int nt = nth * 4 + n4;
                float ba = sb1[nt * 8 + 2 * q], bb = sb1[nt * 8 + 2 * q + 1];
                int ktA = nt >> 1, rg = (nt & 1) * 2;
#pragma unroll
                for (int mt = 0; mt < 2; mt++) {
                    float x0 = fmaxf(hc[mt][n4][0] + ba, 0.f);
                    float x1 = fmaxf(hc[mt][n4][1] + bb, 0.f);
                    float x2 = fmaxf(hc[mt][n4][2] + ba, 0.f);
                    float x3 = fmaxf(hc[mt][n4][3] + bb, 0.f);
                    split2(x0, x1, awh[mt][ktA][rg],     awl[mt][ktA][rg]);
                    split2(x2, x3, awh[mt][ktA][rg + 1], awl[mt][ktA][rg + 1]);
                }
            }
        }
    }
    __syncthreads();           // EF/W1F scratch dead -> B buffers may be written

    // ---- B chunk0 cp.async (overlaps tmp compute) ----
    {
        const uint4* bf = (const uint4*)g_Bf;
        for (int r = tid; r < 1024; r += 128) cpa16(base + S_B + r * 16, bf + r);
        CP_COMMIT();
    }

    // ---- tmp: tmp[e, m*2+l] = sum_d f[src,m,d]*basis1[e,d,l] ----
    {
        int e = blk * 128 + tid;
        int src = __ldg(&nbr[e]);
        const float4* fp = (const float4*)(f + (size_t)src * 32);
        float fr[8][4];
#pragma unroll
        for (int m = 0; m < 8; m++) {
            float4 v = __ldg(&fp[m]);
            fr[m][0] = v.x; fr[m][1] = v.y; fr[m][2] = v.z; fr[m][3] = v.w;
        }
        float4 b0 = __ldg((const float4*)(basis1 + (size_t)e * 8));
        float4 b1v = __ldg((const float4*)(basis1 + (size_t)e * 8 + 4));
        float bd[4][2] = {{b0.x, b0.y}, {b0.z, b0.w}, {b1v.x, b1v.y}, {b1v.z, b1v.w}};
        float* dst = (float*)(sm + S_TMP);
#pragma unroll
        for (int m = 0; m < 8; m++)
#pragma unroll
            for (int l = 0; l < 2; l++) {
                float a = fr[m][0] * bd[0][l];
                a = fmaf(fr[m][1], bd[1][l], a);
                a = fmaf(fr[m][2], bd[2][l], a);
                a = fmaf(fr[m][3], bd[3][l], a);
                dst[(m * 2 + l) * 128 + tid] = a;
            }
    }
    __syncthreads();           // tmp visible

    float tr[4][4];
    {
        const float* sTMPf = (const float*)(sm + S_TMP);
#pragma unroll
        for (int rid = 0; rid < 4; rid++) {
            int row = wid * 32 + (lane >> 2) + rid * 8;
#pragma unroll
            for (int s = 0; s < 4; s++) {
                int i = (s >> 1) * 8 + 2 * q + (s & 1);
                tr[rid][s] = sTMPf[i * 128 + row];
            }
        }
    }

    float acc[2][4][4];
#pragma unroll
    for (int mt = 0; mt < 2; mt++)
#pragma unroll
        for (int n4 = 0; n4 < 4; n4++)
#pragma unroll
            for (int x = 0; x < 4; x++) acc[mt][n4][x] = 0.0f;

    for (int c = 0; c < 12; c++) {
        CP_WAIT(0);        // B(c) resident
        __syncthreads();   // all warps done with buf (c+1)&1 (chunk c-1); tmp reads done (c=0)

        if (c < 11) {      // prefetch B(c+1) into the buffer just freed
            uint32_t dst = base + S_B + (uint32_t)((c + 1) & 1) * 16384u;
            const uint4* bf = (const uint4*)g_Bf + (size_t)(c + 1) * 1024;
            for (int r = tid; r < 1024; r += 128) cpa16(dst + r * 16, bf + r);
            CP_COMMIT();
        }

        const unsigned char* bbuf = sm + S_B + (uint32_t)(c & 1) * 16384u;
#pragma unroll
        for (int ntg = 0; ntg < 2; ntg++) {
            // ---- MMA half: nt in [4*ntg, 4*ntg+4) ----
#pragma unroll
            for (int kt = 0; kt < 4; kt++) {
                uint4 b[4];
#pragma unroll
                for (int n4 = 0; n4 < 4; n4++)
                    b[n4] = *(const uint4*)(bbuf +
                        (uint32_t)(((kt * 8 + ntg * 4 + n4) * 32 + lane) * 16));
#pragma unroll
                for (int ps = 0; ps < 3; ps++)
#pragma unroll
                    for (int n4 = 0; n4 < 4; n4++) {
                        const uint32_t* bp = (ps == 1) ? &b[n4].z : &b[n4].x;
#pragma unroll
                        for (int mt = 0; mt < 2; mt++)
                            mma16816(acc[mt][n4], (ps == 2) ? awl[mt][kt] : awh[mt][kt], bp);
                    }
            }

            // ---- fragment-direct epilogue (half -> one complete plane) ----
            float p[4][2];
#pragma unroll
            for (int rid = 0; rid < 4; rid++) { p[rid][0] = 0.f; p[rid][1] = 0.f; }
#pragma unroll
            for (int mt = 0; mt < 2; mt++)
#pragma unroll
                for (int n4 = 0; n4 < 4; n4++) {
                    int o2 = n4 >> 1, s0 = (n4 & 1) * 2;
                    float2 bb = *(const float2*)&sB2f[c * 64 + (ntg * 4 + n4) * 8 + q * 2];
#pragma unroll
                    for (int h = 0; h < 2; h++) {
                        int rid = mt * 2 + h;
                        p[rid][o2] = fmaf(acc[mt][n4][h * 2] + bb.x, tr[rid][s0],
                                     fmaf(acc[mt][n4][h * 2 + 1] + bb.y, tr[rid][s0 + 1],
                                          p[rid][o2]));
                        acc[mt][n4][h * 2] = 0.0f;
                        acc[mt][n4][h * 2 + 1] = 0.0f;
                    }
                }
#pragma unroll
            for (int rid = 0; rid < 4; rid++)
#pragma unroll
                for (int o2 = 0; o2 < 2; o2++) {
                    p[rid][o2] += __shfl_xor_sync(0xffffffffu, p[rid][o2], 1);
                    p[rid][o2] += __shfl_xor_sync(0xffffffffu, p[rid][o2], 2);
                }

            if (c < 4 || c >= 8) {
                if (q == 0) {
                    int plane = ((c < 4) ? (c * 2) : ((c - 8) * 2 + 8)) + ntg;
#pragma unroll
                    for (int rid = 0; rid < 4; rid++) {
                        int el = wid * 32 + (lane >> 2) + rid * 8;
                        float4 p0 = *(const float4*)(sm + S_BAS + el * 32);
                        float4 p1 = *(const float4*)(sm + S_BAS + el * 32 + 16);
                        float a0 = p[rid][0], a1 = p[rid][1];
                        float4 o4;
                        o4.x = fmaf(a0, p0.x, a1 * p1.x);
                        o4.y = fmaf(a0, p0.y, a1 * p1.y);
                        o4.z = fmaf(a0, p0.z, a1 * p1.z);
                        o4.w = fmaf(a0, p0.w, a1 * p1.w);
                        *(float4*)(sm + S_KQV + (size_t)plane * 2048 + el * 16) = o4;
                    }
                }
            } else {
                int qp = (c - 4) * 2 + ntg;
                float4 an[2];
                an[0] = make_float4(0.f, 0.f, 0.f, 0.f);
                an[1] = make_float4(0.f, 0.f, 0.f, 0.f);
#pragma unroll
                for (int rid = 0; rid < 4; rid++) {
                    int el = wid * 32 + (lane >> 2) + rid * 8;
                    float4 p0 = *(const float4*)(sm + S_BAS + el * 32);
                    float4 p1 = *(const float4*)(sm + S_BAS + el * 32 + 16);
                    int nn = rid >> 1;
                    float a0 = p[rid][0], a1 = p[rid][1];
                    an[nn].x = fmaf(a0, p0.x, fmaf(a1, p1.x, an[nn].x));
                    an[nn].y = fmaf(a0, p0.y, fmaf(a1, p1.y, an[nn].y));
                    an[nn].z = fmaf(a0, p0.z, fmaf(a1, p1.z, an[nn].z));
                    an[nn].w = fmaf(a0, p0.w, fmaf(a1, p1.w, an[nn].w));
                }
#pragma unroll
                for (int nn = 0; nn < 2; nn++)
#pragma unroll
                    for (int d = 4; d <= 16; d <<= 1) {
                        an[nn].x += __shfl_xor_sync(0xffffffffu, an[nn].x, d);
                        an[nn].y += __shfl_xor_sync(0xffffffffu, an[nn].y, d);
                        an[nn].z += __shfl_xor_sync(0xffffffffu, an[nn].z, d);
                        an[nn].w += __shfl_xor_sync(0xffffffffu, an[nn].w, d);
                    }
                if (lane == 0) {
                    *(float4*)(sm + S_QN + (size_t)((wid * 2 + 0) * 8 + qp) * 16) = an[0];
                    *(float4*)(sm + S_QN + (size_t)((wid * 2 + 1) * 8 + qp) * 16) = an[1];
                }
            }
        }
    }

    // ---- in-CTA attention: 8 nodes, 16 lanes per node ----
    __syncthreads();
    {
        int k16 = lane & 15, nh = lane >> 4;
        int nl = wid * 2 + nh;
        int n = blk * 8 + nl;
        int el = nl * 16 + k16;
        float s[4] = {0.f, 0.f, 0.f, 0.f};
#pragma unroll
        for (int pp = 0; pp < 8; pp++) {
            float4 kv = *(const float4*)(sm + S_KQV + (size_t)pp * 2048 + el * 16);
            float4 qv = *(const float4*)(sm + S_QN + (size_t)(nl * 8 + pp) * 16);
            s[pp >> 1] = fmaf(kv.x, qv.x, fmaf(kv.y, qv.y,
                         fmaf(kv.z, qv.z, fmaf(kv.w, qv.w, s[pp >> 1]))));
        }
        const float scale = 0.35355339059327373f * 0.0625f;  // 8^-0.5 * 1/16 (q mean)
#pragma unroll
        for (int h = 0; h < 4; h++) {
            s[h] *= scale;
            float m = s[h];
#pragma unroll
            for (int d = 1; d < 16; d <<= 1)
                m = fmaxf(m, __shfl_xor_sync(0xffffffffu, m, d));
            float w = __expf(s[h] - m);
            float z = w;
#pragma unroll
            for (int d = 1; d < 16; d <<= 1)
                z += __shfl_xor_sync(0xffffffffu, z, d);
            s[h] = w / z;
        }
#pragma unroll
        for (int pp = 0; pp < 8; pp++) {
            float4 vv = *(const float4*)(sm + S_KQV + (size_t)(8 + pp) * 2048 + el * 16);
            float w = s[pp >> 1];
            float4 o4 = make_float4(w * vv.x, w * vv.y, w * vv.z, w * vv.w);
#pragma unroll
            for (int d = 1; d < 16; d <<= 1) {
                o4.x += __shfl_xor_sync(0xffffffffu, o4.x, d);
                o4.y += __shfl_xor_sync(0xffffffffu, o4.y, d);
                o4.z += __shfl_xor_sync(0xffffffffu, o4.z, d);
                o4.w += __shfl_xor_sync(0xffffffffu, o4.w, d);
            }
            if (k16 == 0)
                *(float4*)(out + (size_t)n * 32 + pp * 4) = o4;
        }
    }
}

extern "C" void kernel_launch(void* const* d_in, const int* in_sizes, int n_in,
                              void* d_out, int out_size) {
    const float* basis1 = (const float*)d_in[0];
    const float* basis2 = (const float*)d_in[1];
    const float* ef     = (const float*)d_in[2];
    const float* f      = (const float*)d_in[3];
    const float* W1     = (const float*)d_in[4];
    const float* b1     = (const float*)d_in[5];
    const float* W2     = (const float*)d_in[6];
    const float* b2     = (const float*)d_in[7];
    const int*   nbr    = (const int*)d_in[8];
    float* out = (float*)d_out;

    cudaFuncSetAttribute(k_main, cudaFuncAttributeMaxDynamicSharedMemorySize, SMEM_SZ);

    k_prep<<<13, 128>>>(W2, W1);
    k_main<<<EN / 128, 128, SMEM_SZ>>>(b2, basis2, basis1, f, nbr, ef, b1, out);
}

// round 10
// speedup vs baseline: 4.3461x; 1.0189x over previous
#include <cuda_runtime.h>
#include <cuda_bf16.h>
#include <cstdint>

#define EN 160000      // edges = N*K
#define NN 10000       // nodes

// ---------------- static device scratch -----------------------------------------------------
__device__ __align__(16) uint4 g_Bf[12 * 1024];   // W2 packed {hi0,hi1,lo0,lo1} [chunk][kt][nt][lane]
__device__ __align__(16) uint4 g_W1f[512];        // W1 packed [kt2(2)][nt(8)][lane]

// ---------------- helpers --------------------------------------------------------------------
__device__ __forceinline__ uint32_t smem_u32(const void* p) {
    uint32_t a;
    asm("{ .reg .u64 t; cvta.to.shared.u64 t, %1; cvt.u32.u64 %0, t; }" : "=r"(a) : "l"(p));
    return a;
}
__device__ __forceinline__ void mma16816(float* c, const uint32_t* a, const uint32_t* b) {
    asm volatile("mma.sync.aligned.m16n8k16.row.col.f32.bf16.bf16.f32 "
        "{%0,%1,%2,%3}, {%4,%5,%6,%7}, {%8,%9}, {%0,%1,%2,%3};"
        : "+f"(c[0]), "+f"(c[1]), "+f"(c[2]), "+f"(c[3])
        : "r"(a[0]), "r"(a[1]), "r"(a[2]), "r"(a[3]), "r"(b[0]), "r"(b[1]));
}
__device__ __forceinline__ void cpa16(uint32_t dst, const void* src) {
    asm volatile("cp.async.cg.shared.global [%0], [%1], 16;" :: "r"(dst), "l"(src));
}
#define CP_COMMIT() asm volatile("cp.async.commit_group;" ::: "memory")
#define CP_WAIT(n)  asm volatile("cp.async.wait_group %0;" :: "n"(n) : "memory")

__device__ __forceinline__ void split2(float a, float b, uint32_t& h, uint32_t& l) {
    __nv_bfloat16 ah = __float2bfloat16(a), bh = __float2bfloat16(b);
    __nv_bfloat16 al = __float2bfloat16(a - __bfloat162float(ah));
    __nv_bfloat16 bl = __float2bfloat16(b - __bfloat162float(bh));
    h = (uint32_t)__bfloat16_as_ushort(ah) | ((uint32_t)__bfloat16_as_ushort(bh) << 16);
    l = (uint32_t)__bfloat16_as_ushort(al) | ((uint32_t)__bfloat16_as_ushort(bl) << 16);
}

// ---------------- Kernel P: pack W2 (12 blocks) and W1 (block 12), hi/lo interleaved ---------
__global__ void k_prep(const float* __restrict__ W2, const float* __restrict__ W1) {
    int bid = blockIdx.x, tid = threadIdx.x;
    if (bid < 12) {
        int c = bid;
        for (int idx = tid; idx < 1024; idx += 128) {
            int kt = idx >> 8, nt = (idx >> 5) & 7, l = idx & 31;
            int row = c * 64 + nt * 8 + (l >> 2);
            int j0 = kt * 16 + (l & 3) * 2;
            const float* wr = W2 + (size_t)row * 64;
            uint4 v;
            split2(__ldg(&wr[j0]),     __ldg(&wr[j0 + 1]), v.x, v.z);
            split2(__ldg(&wr[j0 + 8]), __ldg(&wr[j0 + 9]), v.y, v.w);
            g_Bf[c * 1024 + idx] = v;
        }
    } else {
        for (int idx = tid; idx < 512; idx += 128) {
            int kt = idx >> 8, nt = (idx >> 5) & 7, l = idx & 31;
            int j = nt * 8 + (l >> 2);          // N dim = hidden j (64)
            int c0 = kt * 16 + (l & 3) * 2;     // K dim = edge-feat c (32)
            const float* wr = W1 + (size_t)j * 32;
            uint4 v;
            split2(__ldg(&wr[c0]),     __ldg(&wr[c0 + 1]), v.x, v.z);
            split2(__ldg(&wr[c0 + 8]), __ldg(&wr[c0 + 9]), v.y, v.w);
            g_W1f[idx] = v;
        }
    }
}

// ---------------- Kernel A: MLP(HMMA) + GEMM(HMMA) + epilogue + in-CTA attention -------------
// CTA = 128 edges = 8 nodes; 3 CTAs/SM. B fragments via direct __ldg (L2-resident, L1-cached):
// NO barriers in the main loop — warps free-run and de-phase, overlapping epilogue with MMA.
// Smem: KQV planes (prologue-aliased by EF/W1F scratch) + QN + b2 + basis2. 41KB/CTA.
#define S_KQV  0u              // 16 planes x 128 x 16B = 32768
#define S_TMP  0u              //   tmp 8K aliases planes 0-3 (dead before plane writes)
#define S_EF   0u              //   prologue scratch: 128 x 144B = 18432 (dead before tmp)
#define S_W1F  18432u          //   prologue scratch: 8192 (dead before v-plane writes)
#define S_B1   26624u          //   prologue scratch: 256
#define S_QN   32768u          // 1024
#define S_B2   33792u          // 3072  ..36864
#define S_BAS  36864u          // 4096  ..40960
#define SMEM_SZ (40960u + 1024u)

__global__ void __launch_bounds__(128, 3) k_main(const float* __restrict__ b2,
                                                 const float* __restrict__ basis2,
                                                 const float* __restrict__ basis1,
                                                 const float* __restrict__ f,
                                                 const int* __restrict__ nbr,
                                                 const float* __restrict__ ef,
                                                 const float* __restrict__ b1,
                                                 float* __restrict__ out) {
    extern __shared__ unsigned char smraw[];
    uint32_t base = (smem_u32(smraw) + 1023u) & ~1023u;
    unsigned char* sm = smraw + (base - smem_u32(smraw));
    const float* sB2f = (const float*)(sm + S_B2);
    int tid = threadIdx.x, blk = blockIdx.x;
    int wid = tid >> 5, lane = tid & 31;
    int q = lane & 3;

    // ---- prologue: ef tile + W1 frags + b1 + b2 + basis2 ----
    {
        for (int r = tid; r < 1024; r += 128) {
            int row = r >> 3, seg = r & 7;
            cpa16(base + S_EF + (uint32_t)row * 144u + (uint32_t)seg * 16u,
                  ef + ((size_t)(blk * 128 + row)) * 32 + seg * 4);
        }
        const uint4* wf = (const uint4*)g_W1f;
        for (int r = tid; r < 512; r += 128) cpa16(base + S_W1F + r * 16, wf + r);
        const uint4* g1 = (const uint4*)b1;
        for (int r = tid; r < 16; r += 128) cpa16(base + S_B1 + r * 16, g1 + r);
        const uint4* g2 = (const uint4*)b2;
        for (int r = tid; r < 192; r += 128) cpa16(base + S_B2 + r * 16, g2 + r);
        const uint4* gb = (const uint4*)(basis2 + (size_t)blk * 1024);
        for (int r = tid; r < 256; r += 128) cpa16(base + S_BAS + r * 16, gb + r);
        CP_COMMIT();
    }
    CP_WAIT(0);
    __syncthreads();

    // ---- MLP on tensor cores: h = relu(ef @ W1^T + b1) -> A frags in-register ----
    uint32_t awh[2][4][4], awl[2][4][4];   // main-GEMM A frags [mt][kt][r]
    {
        uint32_t efh[2][2][4], efl[2][2][4];
        const float* sEF = (const float*)(sm + S_EF);
#pragma unroll
        for (int mt = 0; mt < 2; mt++)
#pragma unroll
            for (int kt = 0; kt < 2; kt++) {
                int r0 = wid * 32 + mt * 16 + (lane >> 2);
                int c0 = kt * 16 + 2 * q;
                float2 v0 = *(const float2*)&sEF[r0 * 36 + c0];
                float2 v1 = *(const float2*)&sEF[(r0 + 8) * 36 + c0];
                float2 v2 = *(const float2*)&sEF[r0 * 36 + c0 + 8];
                float2 v3 = *(const float2*)&sEF[(r0 + 8) * 36 + c0 + 8];
                split2(v0.x, v0.y, efh[mt][kt][0], efl[mt][kt][0]);
                split2(v1.x, v1.y, efh[mt][kt][1], efl[mt][kt][1]);
                split2(v2.x, v2.y, efh[mt][kt][2], efl[mt][kt][2]);
                split2(v3.x, v3.y, efh[mt][kt][3], efl[mt][kt][3]);
            }
        const float* sb1 = (const float*)(sm + S_B1);
#pragma unroll
        for (int nth = 0; nth < 2; nth++) {
            float hc[2][4][4];
#pragma unroll
            for (int mt = 0; mt < 2; mt++)
#pragma unroll
                for (int n4 = 0; n4 < 4; n4++)
#pragma unroll
                    for (int x = 0; x < 4; x++) hc[mt][n4][x] = 0.0f;
#pragma unroll
            for (int kt2 = 0; kt2 < 2; kt2++) {
                uint4 w[4];
#pragma unroll
                for (int n4 = 0; n4 < 4; n4++)
                    w[n4] = *(const uint4*)(sm + S_W1F +
                        (uint32_t)(((kt2 * 8 + nth * 4 + n4) * 32 + lane) * 16));
#pragma unroll
                for (int ps = 0; ps < 3; ps++)
#pragma unroll
                    for (int n4 = 0; n4 < 4; n4++) {
                        const uint32_t* bp = (ps == 1) ? &w[n4].z : &w[n4].x;
#pragma unroll
                        for (int mt = 0; mt < 2; mt++)
                            mma16816(hc[mt][n4], (ps == 2) ? efl[mt][kt2] : efh[mt][kt2], bp);
                    }
            }
#pragma unroll
            for (int n4 = 0; n4 < 4; n4++) {
                int nt = nth * 4 + n4;
                float ba = sb1[nt * 8 + 2 * q], bb = sb1[nt * 8 + 2 * q + 1];
                int ktA = nt >> 1, rg = (nt & 1) * 2;
#pragma unroll
                for (int mt = 0; mt < 2; mt++) {
                    float x0 = fmaxf(hc[mt][n4][0] + ba, 0.f);
                    float x1 = fmaxf(hc[mt][n4][1] + bb, 0.f);
                    float x2 = fmaxf(hc[mt][n4][2] + ba, 0.f);
                    float x3 = fmaxf(hc[mt][n4][3] + bb, 0.f);
                    split2(x0, x1, awh[mt][ktA][rg],     awl[mt][ktA][rg]);
                    split2(x2, x3, awh[mt][ktA][rg + 1], awl[mt][ktA][rg + 1]);
                }
            }
        }
    }
    __syncthreads();           // EF/W1F/B1 scratch dead for all warps

    // ---- tmp: tmp[e, m*2+l] = sum_d f[src,m,d]*basis1[e,d,l] ----
    {
        int e = blk * 128 + tid;
        int src = __ldg(&nbr[e]);
        const float4* fp = (const float4*)(f + (size_t)src * 32);
        float fr[8][4];
#pragma unroll
        for (int m = 0; m < 8; m++) {
            float4 v = __ldg(&fp[m]);
            fr[m][0] = v.x; fr[m][1] = v.y; fr[m][2] = v.z; fr[m][3] = v.w;
        }
        float4 b0 = __ldg((const float4*)(basis1 + (size_t)e * 8));
        float4 b1v = __ldg((const float4*)(basis1 + (size_t)e * 8 + 4));
        float bd[4][2] = {{b0.x, b0.y}, {b0.z, b0.w}, {b1v.x, b1v.y}, {b1v.z, b1v.w}};
        float* dst = (float*)(sm + S_TMP);
#pragma unroll
        for (int m = 0; m < 8; m++)
#pragma unroll
            for (int l = 0; l < 2; l++) {
                float a = fr[m][0] * bd[0][l];
                a = fmaf(fr[m][1], bd[1][l], a);
                a = fmaf(fr[m][2], bd[2][l], a);
                a = fmaf(fr[m][3], bd[3][l], a);
                dst[(m * 2 + l) * 128 + tid] = a;
            }
    }
    __syncthreads();           // tmp visible to all warps

    float tr[4][4];
    {
        const float* sTMPf = (const float*)(sm + S_TMP);
#pragma unroll
        for (int rid = 0; rid < 4; rid++) {
            int row = wid * 32 + (lane >> 2) + rid * 8;
#pragma unroll
            for (int s = 0; s < 4; s++) {
                int i = (s >> 1) * 8 + 2 * q + (s & 1);
                tr[rid][s] = sTMPf[i * 128 + row];
            }
        }
    }
    __syncthreads();           // ALL warps' tr loaded before plane writes clobber tmp bytes

    float acc[2][4][4];
#pragma unroll
    for (int mt = 0; mt < 2; mt++)
#pragma unroll
        for (int n4 = 0; n4 < 4; n4++)
#pragma unroll
            for (int x = 0; x < 4; x++) acc[mt][n4][x] = 0.0f;

    // ==== free-running main loop: NO barriers; each warp writes only its own smem rows ====
    for (int c = 0; c < 12; c++) {
        const uint4* bc = g_Bf + (size_t)c * 1024;
#pragma unroll
        for (int ntg = 0; ntg < 2; ntg++) {
#pragma unroll
            for (int kt = 0; kt < 4; kt++) {
                uint4 b[4];
#pragma unroll
                for (int n4 = 0; n4 < 4; n4++)
                    b[n4] = __ldg(&bc[(size_t)((kt * 8 + ntg * 4 + n4) * 32 + lane)]);
#pragma unroll
                for (int ps = 0; ps < 3; ps++)
#pragma unroll
                    for (int n4 = 0; n4 < 4; n4++) {
                        const uint32_t* bp = (ps == 1) ? &b[n4].z : &b[n4].x;
#pragma unroll
                        for (int mt = 0; mt < 2; mt++)
                            mma16816(acc[mt][n4], (ps == 2) ? awl[mt][kt] : awh[mt][kt], bp);
                    }
            }

            // ---- fragment-direct epilogue (half -> one complete plane) ----
            float p[4][2];
#pragma unroll
            for (int rid = 0; rid < 4; rid++) { p[rid][0] = 0.f; p[rid][1] = 0.f; }
#pragma unroll
            for (int mt = 0; mt < 2; mt++)
#pragma unroll
                for (int n4 = 0; n4 < 4; n4++) {
                    int o2 = n4 >> 1, s0 = (n4 & 1) * 2;
                    float2 bb = *(const float2*)&sB2f[c * 64 + (ntg * 4 + n4) * 8 + q * 2];
#pragma unroll
                    for (int h = 0; h < 2; h++) {
                        int rid = mt * 2 + h;
                        p[rid][o2] = fmaf(acc[mt][n4][h * 2] + bb.x, tr[rid][s0],
                                     fmaf(acc[mt][n4][h * 2 + 1] + bb.y, tr[rid][s0 + 1],
                                          p[rid][o2]));
                        acc[mt][n4][h * 2] = 0.0f;
                        acc[mt][n4][h * 2 + 1] = 0.0f;
                    }
                }
#pragma unroll
            for (int rid = 0; rid < 4; rid++)
#pragma unroll
                for (int o2 = 0; o2 < 2; o2++) {
                    p[rid][o2] += __shfl_xor_sync(0xffffffffu, p[rid][o2], 1);
                    p[rid][o2] += __shfl_xor_sync(0xffffffffu, p[rid][o2], 2);
                }

            if (c < 4 || c >= 8) {
                if (q == 0) {
                    int plane = ((c < 4) ? (c * 2) : ((c - 8) * 2 + 8)) + ntg;
#pragma unroll
                    for (int rid = 0; rid < 4; rid++) {
                        int el = wid * 32 + (lane >> 2) + rid * 8;
                        float4 p0 = *(const float4*)(sm + S_BAS + el * 32);
                        float4 p1 = *(const float4*)(sm + S_BAS + el * 32 + 16);
                        float a0 = p[rid][0], a1 = p[rid][1];
                        float4 o4;
                        o4.x = fmaf(a0, p0.x, a1 * p1.x);
                        o4.y = fmaf(a0, p0.y, a1 * p1.y);
                        o4.z = fmaf(a0, p0.z, a1 * p1.z);
                        o4.w = fmaf(a0, p0.w, a1 * p1.w);
                        *(float4*)(sm + S_KQV + (size_t)plane * 2048 + el * 16) = o4;
                    }
                }
            } else {
                int qp = (c - 4) * 2 + ntg;
                float4 an[2];
                an[0] = make_float4(0.f, 0.f, 0.f, 0.f);
                an[1] = make_float4(0.f, 0.f, 0.f, 0.f);
#pragma unroll
                for (int rid = 0; rid < 4; rid++) {
                    int el = wid * 32 + (lane >> 2) + rid * 8;
                    float4 p0 = *(const float4*)(sm + S_BAS + el * 32);
                    float4 p1 = *(const float4*)(sm + S_BAS + el * 32 + 16);
                    int nn = rid >> 1;
                    float a0 = p[rid][0], a1 = p[rid][1];
                    an[nn].x = fmaf(a0, p0.x, fmaf(a1, p1.x, an[nn].x));
                    an[nn].y = fmaf(a0, p0.y, fmaf(a1, p1.y, an[nn].y));
                    an[nn].z = fmaf(a0, p0.z, fmaf(a1, p1.z, an[nn].z));
                    an[nn].w = fmaf(a0, p0.w, fmaf(a1, p1.w, an[nn].w));
                }
#pragma unroll
                for (int nn = 0; nn < 2; nn++)
#pragma unroll
                    for (int d = 4; d <= 16; d <<= 1) {
                        an[nn].x += __shfl_xor_sync(0xffffffffu, an[nn].x, d);
                        an[nn].y += __shfl_xor_sync(0xffffffffu, an[nn].y, d);
                        an[nn].z += __shfl_xor_sync(0xffffffffu, an[nn].z, d);
                        an[nn].w += __shfl_xor_sync(0xffffffffu, an[nn].w, d);
                    }
                if (lane == 0) {
                    *(float4*)(sm + S_QN + (size_t)((wid * 2 + 0) * 8 + qp) * 16) = an[0];
                    *(float4*)(sm + S_QN + (size_t)((wid * 2 + 1) * 8 + qp) * 16) = an[1];
                }
            }
        }
    }

    // ---- in-CTA attention: 8 nodes, 16 lanes per node ----
    __syncthreads();
    {
        int k16 = lane & 15, nh = lane >> 4;
        int nl = wid * 2 + nh;
        int n = blk * 8 + nl;
        int el = nl * 16 + k16;
        float s[4] = {0.f, 0.f, 0.f, 0.f};
#pragma unroll
        for (int pp = 0; pp < 8; pp++) {
            float4 kv = *(const float4*)(sm + S_KQV + (size_t)pp * 2048 + el * 16);
            float4 qv = *(const float4*)(sm + S_QN + (size_t)(nl * 8 + pp) * 16);
            s[pp >> 1] = fmaf(kv.x, qv.x, fmaf(kv.y, qv.y,
                         fmaf(kv.z, qv.z, fmaf(kv.w, qv.w, s[pp >> 1]))));
        }
        const float scale = 0.35355339059327373f * 0.0625f;  // 8^-0.5 * 1/16 (q mean)
#pragma unroll
        for (int h = 0; h < 4; h++) {
            s[h] *= scale;
            float m = s[h];
#pragma unroll
            for (int d = 1; d < 16; d <<= 1)
                m = fmaxf(m, __shfl_xor_sync(0xffffffffu, m, d));
            float w = __expf(s[h] - m);
            float z = w;
#pragma unroll
            for (int d = 1; d < 16; d <<= 1)
                z += __shfl_xor_sync(0xffffffffu, z, d);
            s[h] = w / z;
        }
#pragma unroll
        for (int pp = 0; pp < 8; pp++) {
            float4 vv = *(const float4*)(sm + S_KQV + (size_t)(8 + pp) * 2048 + el * 16);
            float w = s[pp >> 1];
            float4 o4 = make_float4(w * vv.x, w * vv.y, w * vv.z, w * vv.w);
#pragma unroll
            for (int d = 1; d < 16; d <<= 1) {
                o4.x += __shfl_xor_sync(0xffffffffu, o4.x, d);
                o4.y += __shfl_xor_sync(0xffffffffu, o4.y, d);
                o4.z += __shfl_xor_sync(0xffffffffu, o4.z, d);
                o4.w += __shfl_xor_sync(0xffffffffu, o4.w, d);
            }
            if (k16 == 0)
                *(float4*)(out + (size_t)n * 32 + pp * 4) = o4;
        }
    }
}

extern "C" void kernel_launch(void* const* d_in, const int* in_sizes, int n_in,
                              void* d_out, int out_size) {
    const float* basis1 = (const float*)d_in[0];
    const float* basis2 = (const float*)d_in[1];
    const float* ef     = (const float*)d_in[2];
    const float* f      = (const float*)d_in[3];
    const float* W1     = (const float*)d_in[4];
    const float* b1     = (const float*)d_in[5];
    const float* W2     = (const float*)d_in[6];
    const float* b2     = (const float*)d_in[7];
    const int*   nbr    = (const int*)d_in[8];
    float* out = (float*)d_out;

    cudaFuncSetAttribute(k_main, cudaFuncAttributeMaxDynamicSharedMemorySize, SMEM_SZ);

    k_prep<<<13, 128>>>(W2, W1);
    k_main<<<EN / 128, 128, SMEM_SZ>>>(b2, basis2, basis1, f, nbr, ef, b1, out);
}